// round 2
// baseline (speedup 1.0000x reference)
#include <cuda_runtime.h>
#include <math.h>

#define BB 4
#define CC 256
#define TT 16
#define HH 32
#define WW 32
#define KCB 1024
#define GG 16
#define CPG 16
#define HWp (HH*WW)          // 1024
#define THW (TT*HWp)         // 16384
#define NN (BB*THW)          // 65536
#define EPSV 1e-6f

// ---- output layout (float32, concatenated reference outputs) ----
#define SZ_ZQ     (BB*CC*THW)        // 16777216
#define OFF_LOSS  (SZ_ZQ)
#define OFF_LOSS2 (SZ_ZQ+1)
#define OFF_INDS  (SZ_ZQ+2)
#define OFF_INDT  (OFF_INDS+NN)
#define OFF_PERPS (OFF_INDT+NN)
#define OFF_PERPT (OFF_PERPS+1)

// ---- scratch (__device__ globals: allocation-free rule) ----
__device__ float g_zp[NN*CC];        // z transposed to (p, c)
__device__ float g_hn[NN*CC];        // groupnorm output; reused as attention out
__device__ float g_q [NN*CC];        // q; reused as zt -> ztf
__device__ float g_k [NN*CC];
__device__ float g_v [NN*CC];
__device__ float g_dist[NN*KCB];     // distance matrix scratch (reused both branches)
__device__ float g_xsq[NN];
__device__ float g_embsq[2*KCB];
__device__ float g_mu[BB*GG];
__device__ float g_rstd[BB*GG];
__device__ int   g_idx[2*NN];
__device__ float g_avg[2*KCB];
__device__ int   g_hist[2*KCB];
__device__ double g_mse;

// ================= kernels =================

__global__ void zero_kernel() {
    int i = blockIdx.x*256 + threadIdx.x;
    if (i < 2*KCB) { g_avg[i] = 0.f; g_hist[i] = 0; }
    if (i == 0) g_mse = 0.0;
}

__global__ void embsq_kernel(const float* __restrict__ es, const float* __restrict__ et) {
    int i = blockIdx.x*256 + threadIdx.x;       // 0..2047
    if (i >= 2*KCB) return;
    const float* r = (i < KCB) ? (es + (size_t)i*CC) : (et + (size_t)(i-KCB)*CC);
    float s = 0.f;
    for (int c = 0; c < CC; c++) s += r[c]*r[c];
    g_embsq[i] = s;
}

__global__ void __launch_bounds__(256) gn_stats_kernel(const float* __restrict__ z) {
    int bg = blockIdx.x;                         // b*GG+g; group slab is contiguous
    const float* p = z + (size_t)bg * CPG * THW;
    double s = 0.0, s2 = 0.0;
    for (int i = threadIdx.x; i < CPG*THW; i += 256) {
        float v = p[i]; s += v; s2 += (double)v*v;
    }
    __shared__ double ss[256], ss2[256];
    ss[threadIdx.x] = s; ss2[threadIdx.x] = s2;
    __syncthreads();
    for (int k = 128; k; k >>= 1) {
        if (threadIdx.x < k) { ss[threadIdx.x] += ss[threadIdx.x+k]; ss2[threadIdx.x] += ss2[threadIdx.x+k]; }
        __syncthreads();
    }
    if (threadIdx.x == 0) {
        double cnt = (double)(CPG*THW);
        double mu = ss[0]/cnt;
        double var = ss2[0]/cnt - mu*mu;
        g_mu[bg] = (float)mu;
        g_rstd[bg] = rsqrtf((float)var + EPSV);
    }
}

// z (b,c,thw) -> zp (p,c) and hn (p,c) [groupnorm applied]
__global__ void transpose_norm_kernel(const float* __restrict__ z,
                                      const float* __restrict__ gamma,
                                      const float* __restrict__ beta) {
    __shared__ float tl[32][33];
    int b = blockIdx.z, c0 = blockIdx.y*32, s0 = blockIdx.x*32;
    int tx = threadIdx.x, ty = threadIdx.y;
    #pragma unroll
    for (int i = 0; i < 4; i++) {
        int c = c0 + ty + i*8;
        tl[ty + i*8][tx] = z[((size_t)(b*CC + c))*THW + s0 + tx];
    }
    __syncthreads();
    #pragma unroll
    for (int i = 0; i < 4; i++) {
        int th = s0 + ty + i*8;
        int c  = c0 + tx;
        float v = tl[tx][ty + i*8];
        size_t o = ((size_t)(b*THW + th))*CC + c;
        g_zp[o] = v;
        int bg = b*GG + (c >> 4);
        g_hn[o] = (v - g_mu[bg]) * g_rstd[bg] * gamma[c] + beta[c];
    }
}

// Out[r,c] = alpha*(A[r,:] . Bm[c,:]) + (use_rowv ? g_xsq[r] : 0) + colv[c]
__global__ void __launch_bounds__(256) gemm_nt(const float* __restrict__ A,
                                               const float* __restrict__ Bm,
                                               const float* __restrict__ colv,
                                               int use_rowv,
                                               float* __restrict__ Out,
                                               int Ncols, float alpha) {
    __shared__ __align__(16) float As[16][64];
    __shared__ __align__(16) float Bs[16][64];
    int tid = threadIdx.x;
    int tx = tid & 15, ty = tid >> 4;
    int row0 = blockIdx.y*64, col0 = blockIdx.x*64;
    int lr = tid >> 2;
    int lk = (tid & 3) << 2;
    float acc[4][4] = {};
    const float* Ap = A  + (size_t)(row0 + lr)*CC + lk;
    const float* Bp = Bm + (size_t)(col0 + lr)*CC + lk;
    for (int k0 = 0; k0 < CC; k0 += 16) {
        float4 a4 = *(const float4*)(Ap + k0);
        float4 b4 = *(const float4*)(Bp + k0);
        As[lk+0][lr]=a4.x; As[lk+1][lr]=a4.y; As[lk+2][lr]=a4.z; As[lk+3][lr]=a4.w;
        Bs[lk+0][lr]=b4.x; Bs[lk+1][lr]=b4.y; Bs[lk+2][lr]=b4.z; Bs[lk+3][lr]=b4.w;
        __syncthreads();
        #pragma unroll
        for (int kk = 0; kk < 16; kk++) {
            float4 av = *(const float4*)&As[kk][ty << 2];
            float4 bv = *(const float4*)&Bs[kk][tx << 2];
            float ar[4] = {av.x, av.y, av.z, av.w};
            float br[4] = {bv.x, bv.y, bv.z, bv.w};
            #pragma unroll
            for (int i = 0; i < 4; i++)
                #pragma unroll
                for (int j = 0; j < 4; j++)
                    acc[i][j] += ar[i]*br[j];
        }
        __syncthreads();
    }
    #pragma unroll
    for (int i = 0; i < 4; i++) {
        int r = row0 + (ty << 2) + i;
        float rv = use_rowv ? g_xsq[r] : 0.f;
        #pragma unroll
        for (int j = 0; j < 4; j++) {
            int c = col0 + (tx << 2) + j;
            Out[(size_t)r*Ncols + c] = alpha*acc[i][j] + rv + colv[c];
        }
    }
}

// temporal self-attention over t=16 per (b,h,w); reads g_q/g_k/g_v, writes g_hn
__global__ void __launch_bounds__(256) attn_kernel() {
    __shared__ float qs[16][256], ks[16][256];
    __shared__ float att[16][16];
    int x = blockIdx.x;
    int b = x >> 10;
    int s = x & (HWp - 1);
    size_t base = ((size_t)(b*TT)*HWp + s)*CC;
    const size_t tstr = (size_t)HWp*CC;
    int tid = threadIdx.x;
    for (int e = tid; e < 16*256; e += 256) {
        int t = e >> 8, c = e & 255;
        qs[t][c] = g_q[base + (size_t)t*tstr + c];
        ks[t][c] = g_k[base + (size_t)t*tstr + c];
    }
    __syncthreads();
    int i = tid >> 4, j = tid & 15;
    float acc = 0.f;
    #pragma unroll 8
    for (int c = 0; c < 256; c++) acc += qs[i][c]*ks[j][c];
    att[i][j] = acc * 0.0625f;    // C^-0.5 = 1/16
    __syncthreads();
    if (tid < 16) {
        float m = -3.4e38f;
        for (int jj = 0; jj < 16; jj++) m = fmaxf(m, att[tid][jj]);
        float ssum = 0.f;
        for (int jj = 0; jj < 16; jj++) { float e = expf(att[tid][jj]-m); att[tid][jj] = e; ssum += e; }
        float r = 1.0f/ssum;
        for (int jj = 0; jj < 16; jj++) att[tid][jj] *= r;
    }
    __syncthreads();
    int c = tid;
    float vv[16];
    #pragma unroll
    for (int tk = 0; tk < 16; tk++) vv[tk] = g_v[base + (size_t)tk*tstr + c];
    #pragma unroll
    for (int tq = 0; tq < 16; tq++) {
        float o = 0.f;
        #pragma unroll
        for (int tk = 0; tk < 16; tk++) o += att[tq][tk]*vv[tk];
        g_hn[base + (size_t)tq*tstr + c] = o;
    }
}

// ztf = zt + (zp[t] - zp[t-1]); in-place on g_q
__global__ void add_diff_kernel() {
    size_t idx = (size_t)blockIdx.x*256 + threadIdx.x;
    int p = (int)(idx >> 8);
    int t = (p / HWp) % TT;
    float d = 0.f;
    if (t > 0) d = g_zp[idx] - g_zp[idx - (size_t)HWp*CC];
    g_q[idx] += d;
}

__global__ void rowsq_kernel(const float* __restrict__ X) {
    int warp = threadIdx.x >> 5, lane = threadIdx.x & 31;
    int row = blockIdx.x*8 + warp;
    const float* r = X + (size_t)row*CC;
    float s = 0.f;
    for (int c = lane; c < CC; c += 32) s += r[c]*r[c];
    #pragma unroll
    for (int o = 16; o; o >>= 1) s += __shfl_down_sync(0xffffffffu, s, o);
    if (!lane) g_xsq[row] = s;
}

// per 64-row block: argmin + 1/d row-normalization + per-column accumulation
__global__ void __launch_bounds__(256) vq_reduce_kernel(int branch) {
    __shared__ float sinv[1024];
    __shared__ float sacc[1024];
    __shared__ float rs[256];
    __shared__ float rmv[256];
    __shared__ int   rmi[256];
    __shared__ float rowsum_sh;
    int tid = threadIdx.x;
    #pragma unroll
    for (int j = 0; j < 4; j++) sacc[tid + j*256] = 0.f;
    int row0 = blockIdx.x * 64;
    for (int r = 0; r < 64; r++) {
        int row = row0 + r;
        const float* dr = g_dist + (size_t)row*KCB;
        float lsum = 0.f, lmin = 3.4e38f; int lidx = 0;
        #pragma unroll
        for (int j = 0; j < 4; j++) {
            int c = tid + j*256;
            float d = dr[c];
            float inv = 1.0f/d;
            sinv[c] = inv;
            lsum += inv;
            if (d < lmin) { lmin = d; lidx = c; }
        }
        rs[tid] = lsum; rmv[tid] = lmin; rmi[tid] = lidx;
        __syncthreads();
        for (int s = 128; s; s >>= 1) {
            if (tid < s) {
                rs[tid] += rs[tid+s];
                float v2 = rmv[tid+s]; int i2 = rmi[tid+s];
                if (v2 < rmv[tid] || (v2 == rmv[tid] && i2 < rmi[tid])) { rmv[tid] = v2; rmi[tid] = i2; }
            }
            __syncthreads();
        }
        if (tid == 0) {
            rowsum_sh = rs[0];
            g_idx[branch*NN + row] = rmi[0];
            atomicAdd(&g_hist[branch*KCB + rmi[0]], 1);
        }
        __syncthreads();
        float irs = 1.0f / rowsum_sh;
        #pragma unroll
        for (int j = 0; j < 4; j++) { int c = tid + j*256; sacc[c] += sinv[c]*irs; }
        __syncthreads();
    }
    #pragma unroll
    for (int j = 0; j < 4; j++) {
        int c = tid + j*256;
        atomicAdd(&g_avg[branch*KCB + c], sacc[c]);
    }
}

// z_q assembly + transpose back to (b,c,thw) + MSE accumulation
__global__ void assemble_kernel(const float* __restrict__ emb_s,
                                const float* __restrict__ emb_t,
                                float* __restrict__ out) {
    __shared__ float tl[32][33];
    __shared__ float mred[256];
    int b = blockIdx.z, c0 = blockIdx.y*32, s0 = blockIdx.x*32;
    int tx = threadIdx.x, ty = threadIdx.y;
    float lm = 0.f;
    #pragma unroll
    for (int i = 0; i < 4; i++) {
        int th = s0 + ty + i*8;
        int p = b*THW + th;
        int is = g_idx[p], it = g_idx[NN + p];
        int c = c0 + tx;
        float zpv = g_zp[(size_t)p*CC + c];
        float zq  = emb_t[(size_t)it*CC + c] + emb_s[(size_t)is*CC + c];
        float d = zq - zpv;
        lm += d*d;
        tl[ty + i*8][tx] = zpv + d;    // straight-through: zp + (z_q - zp)
    }
    int tid = ty*32 + tx;
    mred[tid] = lm;
    __syncthreads();
    for (int s = 128; s; s >>= 1) { if (tid < s) mred[tid] += mred[tid+s]; __syncthreads(); }
    if (tid == 0) atomicAdd(&g_mse, (double)mred[0]);
    #pragma unroll
    for (int i = 0; i < 4; i++) {
        int c  = c0 + ty + i*8;
        int th = s0 + tx;
        out[((size_t)(b*CC + c))*THW + th] = tl[tx][ty + i*8];
    }
}

__global__ void ind_write_kernel(float* __restrict__ out) {
    int gid = blockIdx.x*256 + threadIdx.x;   // < 131072
    int br = gid >> 16;
    int o  = gid & (NN - 1);
    int b = o / (TT*HWp);
    int rem = o - b*(TT*HWp);
    int t = rem / HWp;
    int s = rem & (HWp - 1);
    int src = (t*BB + b)*HWp + s;
    out[(br ? OFF_INDT : OFF_INDS) + o] = (float)g_idx[br*NN + src];
}

__global__ void __launch_bounds__(1024) finalize_kernel(float* __restrict__ out) {
    __shared__ double sd[1024];
    int t = threadIdx.x;
    if (t == 0) out[OFF_LOSS] = (float)(1.25 * g_mse / ((double)NN * (double)CC));
    // perplexities
    for (int br = 0; br < 2; br++) {
        double e = (double)g_hist[br*KCB + t] / (double)NN;
        sd[t] = e * log(e + 1e-10);
        __syncthreads();
        for (int s = 512; s; s >>= 1) { if (t < s) sd[t] += sd[t+s]; __syncthreads(); }
        if (t == 0) out[br == 0 ? OFF_PERPS : OFF_PERPT] = (float)exp(-sd[0]);
        __syncthreads();
    }
    // KL-to-uniform
    double kl[2];
    for (int br = 0; br < 2; br++) {
        double a = (double)g_avg[br*KCB + t] / (double)NN;
        sd[t] = a; __syncthreads();
        for (int s = 512; s; s >>= 1) { if (t < s) sd[t] = fmax(sd[t], sd[t+s]); __syncthreads(); }
        double m = sd[0]; __syncthreads();
        sd[t] = exp(a - m); __syncthreads();
        for (int s = 512; s; s >>= 1) { if (t < s) sd[t] += sd[t+s]; __syncthreads(); }
        double Z = sd[0]; __syncthreads();
        sd[t] = a; __syncthreads();
        for (int s = 512; s; s >>= 1) { if (t < s) sd[t] += sd[t+s]; __syncthreads(); }
        double SA = sd[0]; __syncthreads();
        double lse = m + log(Z);
        double tgt = 1.0 / (double)KCB;
        kl[br] = tgt * (log(tgt) + lse - SA / (double)KCB);
    }
    if (t == 0) out[OFF_LOSS2] = (float)(0.1 * (kl[0] + kl[1]));
}

// ================= host =================

extern "C" void kernel_launch(void* const* d_in, const int* in_sizes, int n_in,
                              void* d_out, int out_size) {
    (void)in_sizes; (void)n_in; (void)out_size;
    const float* z     = (const float*)d_in[0];
    const float* emb_s = (const float*)d_in[1];
    const float* emb_t = (const float*)d_in[2];
    const float* gamma = (const float*)d_in[3];
    const float* beta  = (const float*)d_in[4];
    const float* wq = (const float*)d_in[5];
    const float* bq = (const float*)d_in[6];
    const float* wk = (const float*)d_in[7];
    const float* bk = (const float*)d_in[8];
    const float* wv = (const float*)d_in[9];
    const float* bv = (const float*)d_in[10];
    const float* wp = (const float*)d_in[11];
    const float* bp = (const float*)d_in[12];
    float* out = (float*)d_out;

    float *p_zp, *p_hn, *p_q, *p_k, *p_v, *p_dist, *p_embsq;
    cudaGetSymbolAddress((void**)&p_zp, g_zp);
    cudaGetSymbolAddress((void**)&p_hn, g_hn);
    cudaGetSymbolAddress((void**)&p_q,  g_q);
    cudaGetSymbolAddress((void**)&p_k,  g_k);
    cudaGetSymbolAddress((void**)&p_v,  g_v);
    cudaGetSymbolAddress((void**)&p_dist, g_dist);
    cudaGetSymbolAddress((void**)&p_embsq, g_embsq);

    zero_kernel<<<8, 256>>>();
    embsq_kernel<<<8, 256>>>(emb_s, emb_t);
    gn_stats_kernel<<<BB*GG, 256>>>(z);
    transpose_norm_kernel<<<dim3(THW/32, CC/32, BB), dim3(32, 8)>>>(z, gamma, beta);

    // q, k, v = conv1(hn)
    gemm_nt<<<dim3(4, NN/64), 256>>>(p_hn, wq, bq, 0, p_q, CC, 1.0f);
    gemm_nt<<<dim3(4, NN/64), 256>>>(p_hn, wk, bk, 0, p_k, CC, 1.0f);
    gemm_nt<<<dim3(4, NN/64), 256>>>(p_hn, wv, bv, 0, p_v, CC, 1.0f);

    attn_kernel<<<BB*HWp, 256>>>();                               // -> g_hn
    gemm_nt<<<dim3(4, NN/64), 256>>>(p_hn, wp, bp, 0, p_q, CC, 1.0f);  // zt -> g_q
    add_diff_kernel<<<NN, 256>>>();                               // ztf in g_q

    // spatial VQ
    rowsq_kernel<<<NN/8, 256>>>(p_zp);
    gemm_nt<<<dim3(KCB/64, NN/64), 256>>>(p_zp, emb_s, p_embsq, 1, p_dist, KCB, -2.0f);
    vq_reduce_kernel<<<NN/64, 256>>>(0);

    // temporal VQ
    rowsq_kernel<<<NN/8, 256>>>(p_q);
    gemm_nt<<<dim3(KCB/64, NN/64), 256>>>(p_q, emb_t, p_embsq + KCB, 1, p_dist, KCB, -2.0f);
    vq_reduce_kernel<<<NN/64, 256>>>(1);

    assemble_kernel<<<dim3(THW/32, CC/32, BB), dim3(32, 8)>>>(emb_s, emb_t, out);
    ind_write_kernel<<<2*NN/256, 256>>>(out);
    finalize_kernel<<<1, 1024>>>(out);
}

// round 5
// speedup vs baseline: 1.6569x; 1.6569x over previous
#include <cuda_runtime.h>
#include <cuda_fp16.h>
#include <math.h>
#include <cstdint>

#define BB 4
#define CC 256
#define TT 16
#define HH 32
#define WW 32
#define KCB 1024
#define GG 16
#define HWp (HH*WW)          // 1024
#define THW (TT*HWp)         // 16384
#define NN (BB*THW)          // 65536
#define EPSV 1e-6f

// operand scalings (keep fp16 lo-terms in normal range)
#define SXV 64.0f
#define SWV 64.0f
#define SEV 16384.0f
#define ALPHA_CONV (1.0f/(64.0f*64.0f))
#define ALPHA_DIST (-2.0f/(64.0f*16384.0f))
#define REFINE_TH 2e-4f

// ---- output layout ----
#define SZ_ZQ     (BB*CC*THW)
#define OFF_LOSS  (SZ_ZQ)
#define OFF_LOSS2 (SZ_ZQ+1)
#define OFF_INDS  (SZ_ZQ+2)
#define OFF_INDT  (OFF_INDS+NN)
#define OFF_PERPS (OFF_INDT+NN)
#define OFF_PERPT (OFF_PERPS+1)

// ---- scratch ----
__device__ float g_zp[NN*CC];        // zp fp32 (exact, for refinement + assemble)
__device__ float g_q [NN*CC];        // q -> zt -> ztf fp32 (exact, for refinement)
__device__ float g_k [NN*CC];
__device__ float g_v [NN*CC];
__device__ float g_dist[NN*KCB];
__device__ __half g_p1h[NN*CC];      // 64*(hn -> attnout -> ztf) hi
__device__ __half g_p1l[NN*CC];
__device__ __half g_p2h[NN*CC];      // 64*zp hi
__device__ __half g_p2l[NN*CC];
__device__ __half g_wh[4*CC*CC];     // 64*w
__device__ __half g_wl[4*CC*CC];
__device__ __half g_ebh[2*KCB*CC];   // 16384*emb
__device__ __half g_ebl[2*KCB*CC];
__device__ float g_xsq[2*NN];
__device__ float g_embsq[2*KCB];
__device__ float g_mu[BB*GG];
__device__ float g_rstd[BB*GG];
__device__ int   g_idx[2*NN];
__device__ float g_avg[2*KCB];
__device__ int   g_hist[2*KCB];
__device__ double g_mse;

// ================= helpers =================
__device__ __forceinline__ uint32_t smem_u32(const void* p) {
    uint32_t a;
    asm("{ .reg .u64 t; cvta.to.shared.u64 t, %1; cvt.u32.u64 %0, t; }" : "=r"(a) : "l"(p));
    return a;
}
#define CP_ASYNC16(dst, src) \
    asm volatile("cp.async.cg.shared.global [%0], [%1], 16;" :: "r"(dst), "l"(src))
#define CP_COMMIT() asm volatile("cp.async.commit_group;" ::: "memory")
#define CP_WAIT1()  asm volatile("cp.async.wait_group 1;" ::: "memory")

__device__ __forceinline__ void ldsm_x4(uint32_t* r, uint32_t addr) {
    asm volatile("ldmatrix.sync.aligned.m8n8.x4.shared.b16 {%0,%1,%2,%3}, [%4];"
        : "=r"(r[0]), "=r"(r[1]), "=r"(r[2]), "=r"(r[3]) : "r"(addr));
}
__device__ __forceinline__ void mma16816(float* d, const uint32_t* a, const uint32_t* b) {
    asm volatile("mma.sync.aligned.m16n8k16.row.col.f32.f16.f16.f32 "
        "{%0,%1,%2,%3}, {%4,%5,%6,%7}, {%8,%9}, {%0,%1,%2,%3};"
        : "+f"(d[0]), "+f"(d[1]), "+f"(d[2]), "+f"(d[3])
        : "r"(a[0]), "r"(a[1]), "r"(a[2]), "r"(a[3]), "r"(b[0]), "r"(b[1]));
}
__device__ __forceinline__ void split16(float v, __half* hp, __half* lp) {
    __half h = __float2half_rn(v);
    *hp = h;
    *lp = __float2half_rn(v - __half2float(h));
}

// ================= small kernels =================

__global__ void zero_kernel() {
    int i = blockIdx.x*256 + threadIdx.x;
    if (i < 2*KCB) { g_avg[i] = 0.f; g_hist[i] = 0; }
    if (i == 0) g_mse = 0.0;
}

__global__ void embsplit_kernel(const float* __restrict__ es, const float* __restrict__ et) {
    int row = blockIdx.x, c = threadIdx.x;
    const float* src = (row < KCB) ? (es + (size_t)row*CC) : (et + (size_t)(row-KCB)*CC);
    float v = src[c];
    size_t o = (size_t)row*CC + c;
    split16(v*SEV, &g_ebh[o], &g_ebl[o]);
    float s = v*v;
    #pragma unroll
    for (int off = 16; off; off >>= 1) s += __shfl_xor_sync(0xffffffffu, s, off);
    __shared__ float red[8];
    if ((c & 31) == 0) red[c >> 5] = s;
    __syncthreads();
    if (c == 0) {
        float t = 0.f;
        #pragma unroll
        for (int j = 0; j < 8; j++) t += red[j];
        g_embsq[row] = t;
    }
}

__global__ void wsplit_kernel(const float* __restrict__ wq, const float* __restrict__ wk,
                              const float* __restrict__ wv, const float* __restrict__ wp) {
    int i = blockIdx.x*256 + threadIdx.x;
    int seg = i >> 16, j = i & 65535;
    const float* src = seg == 0 ? wq : seg == 1 ? wk : seg == 2 ? wv : wp;
    split16(src[j]*SWV, &g_wh[i], &g_wl[i]);
}

__global__ void __launch_bounds__(256) gn_stats_kernel(const float* __restrict__ z) {
    int bg = blockIdx.x;
    const float* p = z + (size_t)bg * 16 * THW;
    double s = 0.0, s2 = 0.0;
    for (int i = threadIdx.x; i < 16*THW; i += 256) {
        float v = p[i]; s += v; s2 += (double)v*v;
    }
    __shared__ double ss[256], ss2[256];
    ss[threadIdx.x] = s; ss2[threadIdx.x] = s2;
    __syncthreads();
    for (int k = 128; k; k >>= 1) {
        if (threadIdx.x < k) { ss[threadIdx.x] += ss[threadIdx.x+k]; ss2[threadIdx.x] += ss2[threadIdx.x+k]; }
        __syncthreads();
    }
    if (threadIdx.x == 0) {
        double cnt = (double)(16*THW);
        double mu = ss[0]/cnt;
        double var = ss2[0]/cnt - mu*mu;
        g_mu[bg] = (float)mu;
        g_rstd[bg] = rsqrtf((float)var + EPSV);
    }
}

__global__ void transpose_norm_kernel(const float* __restrict__ z,
                                      const float* __restrict__ gamma,
                                      const float* __restrict__ beta) {
    __shared__ float tl[32][33];
    int b = blockIdx.z, c0 = blockIdx.y*32, s0 = blockIdx.x*32;
    int tx = threadIdx.x, ty = threadIdx.y;
    #pragma unroll
    for (int i = 0; i < 4; i++) {
        int c = c0 + ty + i*8;
        tl[ty + i*8][tx] = z[((size_t)(b*CC + c))*THW + s0 + tx];
    }
    __syncthreads();
    #pragma unroll
    for (int i = 0; i < 4; i++) {
        int th = s0 + ty + i*8;
        int c  = c0 + tx;
        float v = tl[tx][ty + i*8];
        size_t o = ((size_t)(b*THW + th))*CC + c;
        g_zp[o] = v;
        split16(v*SXV, &g_p2h[o], &g_p2l[o]);
        int bg = b*GG + (c >> 4);
        float hn = (v - g_mu[bg]) * g_rstd[bg] * gamma[c] + beta[c];
        split16(hn*SXV, &g_p1h[o], &g_p1l[o]);
    }
}

// ================= HMMA 3xFP16 GEMM =================
// Out[r, c] = alpha * (A[r,:].B[c,:]) + (rowv?rowv[r]:0) + colv[c]
// CTA tile 128x128, 8 warps (warp tile 32x64), K=256 chunked by 32, 2-stage cp.async.
// smem: 128 rows x 32 fp16, row pitch 80 bytes (conflict-free ldmatrix).

#define PITCH 80
#define TILE_B (128*PITCH)
#define STAGE_B (4*TILE_B)
#define GSM_TOTAL (2*STAGE_B)     // 81920

__device__ __forceinline__ void g_load_stage(
        uint32_t sb, int stage, int kc,
        const __half* Ah, const __half* Al,
        const __half* Bh, const __half* Bl,
        int row0, int col0, int tid) {
    int k0 = kc*32;
    uint32_t sbase = sb + stage*STAGE_B;
    #pragma unroll
    for (int j = 0; j < 8; j++) {
        int idx = j*256 + tid;
        int t = idx >> 9;
        int r = (idx >> 2) & 127;
        int s = idx & 3;
        const __half* gsrc;
        if (t < 2) gsrc = (t ? Al : Ah) + (size_t)(row0 + r)*CC + k0 + s*8;
        else       gsrc = (t == 2 ? Bh : Bl) + (size_t)(col0 + r)*CC + k0 + s*8;
        uint32_t dst = sbase + t*TILE_B + r*PITCH + s*16;
        CP_ASYNC16(dst, gsrc);
    }
}

__global__ void __launch_bounds__(256)
gemm3fp16(const __half* __restrict__ Ah, const __half* __restrict__ Al,
          const __half* __restrict__ Bh, const __half* __restrict__ Bl,
          const float* __restrict__ colv, const float* __restrict__ rowv,
          float* __restrict__ Out, int out_ld, float alpha) {
    extern __shared__ char smem[];
    uint32_t sb = smem_u32(smem);
    int tid = threadIdx.x, wid = tid >> 5, lane = tid & 31;
    int row0 = blockIdx.y * 128, col0 = blockIdx.x * 128;
    int m_base = (wid & 3) * 32;
    int n_base = (wid >> 2) * 64;

    float acc[2][8][4];
    #pragma unroll
    for (int mt = 0; mt < 2; mt++)
        #pragma unroll
        for (int nt = 0; nt < 8; nt++)
            #pragma unroll
            for (int i = 0; i < 4; i++) acc[mt][nt][i] = 0.f;

    uint32_t a_roff = (uint32_t)(m_base + (lane & 15)) * PITCH + ((lane >> 4) * 16);
    uint32_t b_roff = (uint32_t)(n_base + ((lane >> 4) * 8) + (lane & 7)) * PITCH + (((lane >> 3) & 1) * 16);

    g_load_stage(sb, 0, 0, Ah, Al, Bh, Bl, row0, col0, tid);
    CP_COMMIT();

    for (int kc = 0; kc < 8; kc++) {
        if (kc + 1 < 8) g_load_stage(sb, (kc+1) & 1, kc+1, Ah, Al, Bh, Bl, row0, col0, tid);
        CP_COMMIT();
        CP_WAIT1();
        __syncthreads();
        uint32_t st = sb + (kc & 1)*STAGE_B;
        #pragma unroll
        for (int ks = 0; ks < 2; ks++) {
            uint32_t koff = ks * 32;
            uint32_t ah[2][4], al[2][4], bh[8][2], bl[8][2];
            #pragma unroll
            for (int mt = 0; mt < 2; mt++) {
                uint32_t ad = st + a_roff + (uint32_t)mt*16*PITCH + koff;
                ldsm_x4(ah[mt], ad);
                ldsm_x4(al[mt], ad + TILE_B);
            }
            #pragma unroll
            for (int p = 0; p < 4; p++) {
                uint32_t r4[4];
                uint32_t bd = st + 2*TILE_B + b_roff + (uint32_t)p*16*PITCH + koff;
                ldsm_x4(r4, bd);
                bh[2*p][0] = r4[0]; bh[2*p][1] = r4[1];
                bh[2*p+1][0] = r4[2]; bh[2*p+1][1] = r4[3];
                ldsm_x4(r4, bd + TILE_B);
                bl[2*p][0] = r4[0]; bl[2*p][1] = r4[1];
                bl[2*p+1][0] = r4[2]; bl[2*p+1][1] = r4[3];
            }
            #pragma unroll
            for (int mt = 0; mt < 2; mt++)
                #pragma unroll
                for (int nt = 0; nt < 8; nt++) {
                    mma16816(acc[mt][nt], ah[mt], bh[nt]);
                    mma16816(acc[mt][nt], ah[mt], bl[nt]);
                    mma16816(acc[mt][nt], al[mt], bh[nt]);
                }
        }
        __syncthreads();
    }

    int g = lane >> 2, t4 = lane & 3;
    #pragma unroll
    for (int mt = 0; mt < 2; mt++) {
        int r_lo = row0 + m_base + mt*16 + g;
        int r_hi = r_lo + 8;
        float rv_lo = rowv ? rowv[r_lo] : 0.f;
        float rv_hi = rowv ? rowv[r_hi] : 0.f;
        #pragma unroll
        for (int nt = 0; nt < 8; nt++) {
            int c = col0 + n_base + nt*8 + 2*t4;
            float cv0 = colv[c], cv1 = colv[c+1];
            float2 vlo = make_float2(fmaf(alpha, acc[mt][nt][0], rv_lo + cv0),
                                     fmaf(alpha, acc[mt][nt][1], rv_lo + cv1));
            float2 vhi = make_float2(fmaf(alpha, acc[mt][nt][2], rv_hi + cv0),
                                     fmaf(alpha, acc[mt][nt][3], rv_hi + cv1));
            *(float2*)(Out + (size_t)r_lo*out_ld + c) = vlo;
            *(float2*)(Out + (size_t)r_hi*out_ld + c) = vhi;
        }
    }
}

// ================= attention =================
__global__ void __launch_bounds__(256) attn_kernel() {
    __shared__ float qs[16][256], ks[16][256];
    __shared__ float att[16][16];
    int x = blockIdx.x;
    int b = x >> 10;
    int s = x & (HWp - 1);
    size_t base = ((size_t)(b*TT)*HWp + s)*CC;
    const size_t tstr = (size_t)HWp*CC;
    int tid = threadIdx.x;
    for (int e = tid; e < 16*256; e += 256) {
        int t = e >> 8, c = e & 255;
        qs[t][c] = g_q[base + (size_t)t*tstr + c];
        ks[t][c] = g_k[base + (size_t)t*tstr + c];
    }
    __syncthreads();
    int i = tid >> 4, j = tid & 15;
    float acc = 0.f;
    #pragma unroll 8
    for (int c = 0; c < 256; c++) acc += qs[i][c]*ks[j][c];
    att[i][j] = acc * 0.0625f;
    __syncthreads();
    if (tid < 16) {
        float m = -3.4e38f;
        for (int jj = 0; jj < 16; jj++) m = fmaxf(m, att[tid][jj]);
        float ssum = 0.f;
        for (int jj = 0; jj < 16; jj++) { float e = expf(att[tid][jj]-m); att[tid][jj] = e; ssum += e; }
        float r = 1.0f/ssum;
        for (int jj = 0; jj < 16; jj++) att[tid][jj] *= r;
    }
    __syncthreads();
    int c = tid;
    float vv[16];
    #pragma unroll
    for (int tk = 0; tk < 16; tk++) vv[tk] = g_v[base + (size_t)tk*tstr + c];
    #pragma unroll
    for (int tq = 0; tq < 16; tq++) {
        float o = 0.f;
        #pragma unroll
        for (int tk = 0; tk < 16; tk++) o += att[tq][tk]*vv[tk];
        size_t oi = base + (size_t)tq*tstr + c;
        split16(o*SXV, &g_p1h[oi], &g_p1l[oi]);
    }
}

// ztf = zt + diff; keep fp32 in g_q (for refinement), split scaled to pair1, xsq branch1
__global__ void add_diff_kernel() {
    int p = blockIdx.x, c = threadIdx.x;
    size_t idx = (size_t)p*CC + c;
    int t = (p / HWp) % TT;
    float d = 0.f;
    if (t > 0) d = g_zp[idx] - g_zp[idx - (size_t)HWp*CC];
    float v = g_q[idx] + d;
    g_q[idx] = v;
    split16(v*SXV, &g_p1h[idx], &g_p1l[idx]);
    float s = v*v;
    #pragma unroll
    for (int o = 16; o; o >>= 1) s += __shfl_xor_sync(0xffffffffu, s, o);
    __shared__ float red[8];
    if ((c & 31) == 0) red[c >> 5] = s;
    __syncthreads();
    if (c == 0) {
        float tt = 0.f;
        #pragma unroll
        for (int j = 0; j < 8; j++) tt += red[j];
        g_xsq[NN + p] = tt;
    }
}

__global__ void rowsq_kernel(const float* __restrict__ X) {
    int warp = threadIdx.x >> 5, lane = threadIdx.x & 31;
    int row = blockIdx.x*8 + warp;
    const float* r = X + (size_t)row*CC;
    float s = 0.f;
    for (int c = lane; c < CC; c += 32) s += r[c]*r[c];
    #pragma unroll
    for (int o = 16; o; o >>= 1) s += __shfl_down_sync(0xffffffffu, s, o);
    if (!lane) g_xsq[row] = s;
}

// warp-per-row: argmin (top-2 + fp32 refinement) + 1/d rownorm + column accumulation
__global__ void __launch_bounds__(256) vq_reduce_kernel(int branch, const float* __restrict__ X,
                                                        const float* __restrict__ EMB) {
    __shared__ float sacc[1024];
    int tid = threadIdx.x, w = tid >> 5, lane = tid & 31;
    for (int i = tid; i < 1024; i += 256) sacc[i] = 0.f;
    __syncthreads();
    int row0 = blockIdx.x * 64;
    float acc[32];
    #pragma unroll
    for (int j = 0; j < 32; j++) acc[j] = 0.f;
    for (int rr = 0; rr < 8; rr++) {
        int row = row0 + w*8 + rr;
        const float* dr = g_dist + (size_t)row*KCB;
        float inv[32];
        float lsum = 0.f, m1 = 3.4e38f, m2 = 3.4e38f; int i1 = 0;
        #pragma unroll
        for (int j = 0; j < 32; j++) {
            float d = dr[j*32 + lane];
            float iv = 1.0f/d;
            inv[j] = iv; lsum += iv;
            if (d < m1) { m2 = m1; m1 = d; i1 = j*32 + lane; }
            else if (d < m2) m2 = d;
        }
        #pragma unroll
        for (int o = 16; o; o >>= 1) {
            lsum += __shfl_xor_sync(0xffffffffu, lsum, o);
            float o1 = __shfl_xor_sync(0xffffffffu, m1, o);
            int   oi = __shfl_xor_sync(0xffffffffu, i1, o);
            float o2 = __shfl_xor_sync(0xffffffffu, m2, o);
            if (o1 < m1 || (o1 == m1 && oi < i1)) { m2 = fminf(m1, o2); m1 = o1; i1 = oi; }
            else m2 = fminf(m2, fminf(o1, o2) == o1 ? o1 : o1);  // m2 = min(m2, o1)
        }
        int idxf = i1;
        if (m2 - m1 <= REFINE_TH) {
            // exact fp32 re-check over all candidates within the window
            float xr[8];
            #pragma unroll
            for (int k = 0; k < 8; k++) xr[k] = X[(size_t)row*CC + lane + 32*k];
            float sA = g_xsq[branch*NN + row];
            float thr = m1 + REFINE_TH;
            float bestd = 3.4e38f; int besti = 0;
            for (int j = 0; j < 32; j++) {
                float d = dr[j*32 + lane];
                unsigned bal = __ballot_sync(0xffffffffu, d <= thr);
                while (bal) {
                    int src = __ffs(bal) - 1; bal &= bal - 1;
                    int cidx = j*32 + src;
                    const float* er = EMB + (size_t)cidx*CC;
                    float dot = 0.f;
                    #pragma unroll
                    for (int k = 0; k < 8; k++) dot = fmaf(xr[k], er[lane + 32*k], dot);
                    #pragma unroll
                    for (int o = 16; o; o >>= 1) dot += __shfl_xor_sync(0xffffffffu, dot, o);
                    float de = fmaf(-2.f, dot, sA + g_embsq[branch*KCB + cidx]);
                    if (de < bestd) { bestd = de; besti = cidx; }  // increasing cidx -> first-min kept
                }
            }
            idxf = besti;
        }
        if (lane == 0) {
            g_idx[branch*NN + row] = idxf;
            atomicAdd(&g_hist[branch*KCB + idxf], 1);
        }
        float irs = 1.0f/lsum;
        #pragma unroll
        for (int j = 0; j < 32; j++) acc[j] += inv[j]*irs;
    }
    #pragma unroll
    for (int j = 0; j < 32; j++) atomicAdd(&sacc[j*32 + lane], acc[j]);
    __syncthreads();
    for (int i = tid; i < 1024; i += 256) atomicAdd(&g_avg[branch*KCB + i], sacc[i]);
}

__global__ void assemble_kernel(const float* __restrict__ emb_s,
                                const float* __restrict__ emb_t,
                                float* __restrict__ out) {
    __shared__ float tl[32][33];
    __shared__ float mred[256];
    int b = blockIdx.z, c0 = blockIdx.y*32, s0 = blockIdx.x*32;
    int tx = threadIdx.x, ty = threadIdx.y;
    float lm = 0.f;
    #pragma unroll
    for (int i = 0; i < 4; i++) {
        int th = s0 + ty + i*8;
        int p = b*THW + th;
        int is = g_idx[p], it = g_idx[NN + p];
        int c = c0 + tx;
        float zpv = g_zp[(size_t)p*CC + c];
        float zq  = emb_t[(size_t)it*CC + c] + emb_s[(size_t)is*CC + c];
        float d = zq - zpv;
        lm += d*d;
        tl[ty + i*8][tx] = zpv + d;
    }
    int tid = ty*32 + tx;
    mred[tid] = lm;
    __syncthreads();
    for (int s = 128; s; s >>= 1) { if (tid < s) mred[tid] += mred[tid+s]; __syncthreads(); }
    if (tid == 0) atomicAdd(&g_mse, (double)mred[0]);
    #pragma unroll
    for (int i = 0; i < 4; i++) {
        int c  = c0 + ty + i*8;
        int th = s0 + tx;
        out[((size_t)(b*CC + c))*THW + th] = tl[tx][ty + i*8];
    }
}

__global__ void ind_write_kernel(float* __restrict__ out) {
    int gid = blockIdx.x*256 + threadIdx.x;
    int br = gid >> 16;
    int o  = gid & (NN - 1);
    int b = o / (TT*HWp);
    int rem = o - b*(TT*HWp);
    int t = rem / HWp;
    int s = rem & (HWp - 1);
    int src = (t*BB + b)*HWp + s;
    out[(br ? OFF_INDT : OFF_INDS) + o] = (float)g_idx[br*NN + src];
}

__global__ void __launch_bounds__(1024) finalize_kernel(float* __restrict__ out) {
    __shared__ double sd[1024];
    int t = threadIdx.x;
    if (t == 0) out[OFF_LOSS] = (float)(1.25 * g_mse / ((double)NN * (double)CC));
    for (int br = 0; br < 2; br++) {
        double e = (double)g_hist[br*KCB + t] / (double)NN;
        sd[t] = e * log(e + 1e-10);
        __syncthreads();
        for (int s = 512; s; s >>= 1) { if (t < s) sd[t] += sd[t+s]; __syncthreads(); }
        if (t == 0) out[br == 0 ? OFF_PERPS : OFF_PERPT] = (float)exp(-sd[0]);
        __syncthreads();
    }
    double kl[2];
    for (int br = 0; br < 2; br++) {
        double a = (double)g_avg[br*KCB + t] / (double)NN;
        sd[t] = a; __syncthreads();
        for (int s = 512; s; s >>= 1) { if (t < s) sd[t] = fmax(sd[t], sd[t+s]); __syncthreads(); }
        double m = sd[0]; __syncthreads();
        sd[t] = exp(a - m); __syncthreads();
        for (int s = 512; s; s >>= 1) { if (t < s) sd[t] += sd[t+s]; __syncthreads(); }
        double Z = sd[0]; __syncthreads();
        sd[t] = a; __syncthreads();
        for (int s = 512; s; s >>= 1) { if (t < s) sd[t] += sd[t+s]; __syncthreads(); }
        double SA = sd[0]; __syncthreads();
        double lse = m + log(Z);
        double tgt = 1.0 / (double)KCB;
        kl[br] = tgt * (log(tgt) + lse - SA / (double)KCB);
    }
    if (t == 0) out[OFF_LOSS2] = (float)(0.1 * (kl[0] + kl[1]));
}

// ================= host =================

extern "C" void kernel_launch(void* const* d_in, const int* in_sizes, int n_in,
                              void* d_out, int out_size) {
    (void)in_sizes; (void)n_in; (void)out_size;
    const float* z     = (const float*)d_in[0];
    const float* emb_s = (const float*)d_in[1];
    const float* emb_t = (const float*)d_in[2];
    const float* gamma = (const float*)d_in[3];
    const float* beta  = (const float*)d_in[4];
    const float* wq = (const float*)d_in[5];
    const float* bq = (const float*)d_in[6];
    const float* wk = (const float*)d_in[7];
    const float* bk = (const float*)d_in[8];
    const float* wv = (const float*)d_in[9];
    const float* bv = (const float*)d_in[10];
    const float* wp = (const float*)d_in[11];
    const float* bp = (const float*)d_in[12];
    float* out = (float*)d_out;

    float *p_zp, *p_q, *p_k, *p_v, *p_dist, *p_embsq, *p_xsq;
    __half *p1h, *p1l, *p2h, *p2l, *pwh, *pwl, *pebh, *pebl;
    cudaGetSymbolAddress((void**)&p_zp, g_zp);
    cudaGetSymbolAddress((void**)&p_q,  g_q);
    cudaGetSymbolAddress((void**)&p_k,  g_k);
    cudaGetSymbolAddress((void**)&p_v,  g_v);
    cudaGetSymbolAddress((void**)&p_dist, g_dist);
    cudaGetSymbolAddress((void**)&p_embsq, g_embsq);
    cudaGetSymbolAddress((void**)&p_xsq, g_xsq);
    cudaGetSymbolAddress((void**)&p1h, g_p1h);
    cudaGetSymbolAddress((void**)&p1l, g_p1l);
    cudaGetSymbolAddress((void**)&p2h, g_p2h);
    cudaGetSymbolAddress((void**)&p2l, g_p2l);
    cudaGetSymbolAddress((void**)&pwh, g_wh);
    cudaGetSymbolAddress((void**)&pwl, g_wl);
    cudaGetSymbolAddress((void**)&pebh, g_ebh);
    cudaGetSymbolAddress((void**)&pebl, g_ebl);

    cudaFuncSetAttribute(gemm3fp16, cudaFuncAttributeMaxDynamicSharedMemorySize, GSM_TOTAL);

    zero_kernel<<<8, 256>>>();
    embsplit_kernel<<<2*KCB, 256>>>(emb_s, emb_t);
    wsplit_kernel<<<4*CC*CC/256, 256>>>(wq, wk, wv, wp);
    gn_stats_kernel<<<BB*GG, 256>>>(z);
    transpose_norm_kernel<<<dim3(THW/32, CC/32, BB), dim3(32, 8)>>>(z, gamma, beta);
    rowsq_kernel<<<NN/8, 256>>>(p_zp);

    // q, k, v convs
    gemm3fp16<<<dim3(CC/128, NN/128), 256, GSM_TOTAL>>>(p1h, p1l, pwh,           pwl,           bq, nullptr, p_q, CC, ALPHA_CONV);
    gemm3fp16<<<dim3(CC/128, NN/128), 256, GSM_TOTAL>>>(p1h, p1l, pwh + CC*CC,   pwl + CC*CC,   bk, nullptr, p_k, CC, ALPHA_CONV);
    gemm3fp16<<<dim3(CC/128, NN/128), 256, GSM_TOTAL>>>(p1h, p1l, pwh + 2*CC*CC, pwl + 2*CC*CC, bv, nullptr, p_v, CC, ALPHA_CONV);

    attn_kernel<<<BB*HWp, 256>>>();
    gemm3fp16<<<dim3(CC/128, NN/128), 256, GSM_TOTAL>>>(p1h, p1l, pwh + 3*CC*CC, pwl + 3*CC*CC, bp, nullptr, p_q, CC, ALPHA_CONV);
    add_diff_kernel<<<NN, 256>>>();

    // spatial VQ
    gemm3fp16<<<dim3(KCB/128, NN/128), 256, GSM_TOTAL>>>(p2h, p2l, pebh, pebl,
                                                         p_embsq, p_xsq, p_dist, KCB, ALPHA_DIST);
    vq_reduce_kernel<<<NN/64, 256>>>(0, p_zp, emb_s);

    // temporal VQ
    gemm3fp16<<<dim3(KCB/128, NN/128), 256, GSM_TOTAL>>>(p1h, p1l, pebh + (size_t)KCB*CC, pebl + (size_t)KCB*CC,
                                                         p_embsq + KCB, p_xsq + NN, p_dist, KCB, ALPHA_DIST);
    vq_reduce_kernel<<<NN/64, 256>>>(1, p_q, emb_t);

    assemble_kernel<<<dim3(THW/32, CC/32, BB), dim3(32, 8)>>>(emb_s, emb_t, out);
    ind_write_kernel<<<2*NN/256, 256>>>(out);
    finalize_kernel<<<1, 1024>>>(out);
}

// round 6
// speedup vs baseline: 1.9137x; 1.1550x over previous
#include <cuda_runtime.h>
#include <cuda_fp16.h>
#include <math.h>
#include <cstdint>

#define BB 4
#define CC 256
#define TT 16
#define HH 32
#define WW 32
#define KCB 1024
#define GG 16
#define HWp (HH*WW)          // 1024
#define THW (TT*HWp)         // 16384
#define NN (BB*THW)          // 65536
#define EPSV 1e-6f

// operand scalings (keep fp16 lo-terms in normal range)
#define SXV 64.0f
#define SWV 64.0f
#define SEV 16384.0f
#define ALPHA_CONV (1.0f/(64.0f*64.0f))
#define ALPHA_DIST (-2.0f/(64.0f*16384.0f))
#define REFINE_TH 2e-4f

// ---- output layout ----
#define SZ_ZQ     (BB*CC*THW)
#define OFF_LOSS  (SZ_ZQ)
#define OFF_LOSS2 (SZ_ZQ+1)
#define OFF_INDS  (SZ_ZQ+2)
#define OFF_INDT  (OFF_INDS+NN)
#define OFF_PERPS (OFF_INDT+NN)
#define OFF_PERPT (OFF_PERPS+1)

// ---- scratch ----
__device__ float g_zp[NN*CC];        // zp fp32 (exact, for refinement + assemble)
__device__ float g_q [NN*CC];        // q -> zt -> ztf fp32 (exact, for refinement)
__device__ float g_k [NN*CC];
__device__ float g_v [NN*CC];
__device__ float g_dist[NN*KCB];
__device__ __half g_p1h[NN*CC];      // 64*(hn -> attnout -> ztf) hi
__device__ __half g_p1l[NN*CC];
__device__ __half g_p2h[NN*CC];      // 64*zp hi (single-pass dist: no lo needed)
__device__ __half g_wh[4*CC*CC];     // 64*w
__device__ __half g_wl[4*CC*CC];
__device__ __half g_ebh[2*KCB*CC];   // 16384*emb hi (single-pass dist)
__device__ float g_xsq[2*NN];
__device__ float g_embsq[2*KCB];
__device__ float g_mu[BB*GG];
__device__ float g_rstd[BB*GG];
__device__ double g_sumd[2*BB*GG];   // [bg]=sum, [64+bg]=sumsq
__device__ int   g_idx[2*NN];
__device__ float g_avg[2*KCB];
__device__ int   g_hist[2*KCB];
__device__ double g_mse;

// ================= helpers =================
__device__ __forceinline__ uint32_t smem_u32(const void* p) {
    uint32_t a;
    asm("{ .reg .u64 t; cvta.to.shared.u64 t, %1; cvt.u32.u64 %0, t; }" : "=r"(a) : "l"(p));
    return a;
}
#define CP_ASYNC16(dst, src) \
    asm volatile("cp.async.cg.shared.global [%0], [%1], 16;" :: "r"(dst), "l"(src))
#define CP_COMMIT() asm volatile("cp.async.commit_group;" ::: "memory")
#define CP_WAIT1()  asm volatile("cp.async.wait_group 1;" ::: "memory")

__device__ __forceinline__ void ldsm_x4(uint32_t* r, uint32_t addr) {
    asm volatile("ldmatrix.sync.aligned.m8n8.x4.shared.b16 {%0,%1,%2,%3}, [%4];"
        : "=r"(r[0]), "=r"(r[1]), "=r"(r[2]), "=r"(r[3]) : "r"(addr));
}
__device__ __forceinline__ void mma16816(float* d, const uint32_t* a, const uint32_t* b) {
    asm volatile("mma.sync.aligned.m16n8k16.row.col.f32.f16.f16.f32 "
        "{%0,%1,%2,%3}, {%4,%5,%6,%7}, {%8,%9}, {%0,%1,%2,%3};"
        : "+f"(d[0]), "+f"(d[1]), "+f"(d[2]), "+f"(d[3])
        : "r"(a[0]), "r"(a[1]), "r"(a[2]), "r"(a[3]), "r"(b[0]), "r"(b[1]));
}
__device__ __forceinline__ void split16(float v, __half* hp, __half* lp) {
    __half h = __float2half_rn(v);
    *hp = h;
    *lp = __float2half_rn(v - __half2float(h));
}

// ================= small kernels =================

__global__ void zero_kernel() {
    int i = blockIdx.x*256 + threadIdx.x;
    if (i < 2*KCB) { g_avg[i] = 0.f; g_hist[i] = 0; }
    if (i < 2*BB*GG) g_sumd[i] = 0.0;
    if (i == 0) g_mse = 0.0;
}

__global__ void embsplit_kernel(const float* __restrict__ es, const float* __restrict__ et) {
    int row = blockIdx.x, c = threadIdx.x;
    const float* src = (row < KCB) ? (es + (size_t)row*CC) : (et + (size_t)(row-KCB)*CC);
    float v = src[c];
    g_ebh[(size_t)row*CC + c] = __float2half_rn(v*SEV);
    float s = v*v;
    #pragma unroll
    for (int off = 16; off; off >>= 1) s += __shfl_xor_sync(0xffffffffu, s, off);
    __shared__ float red[8];
    if ((c & 31) == 0) red[c >> 5] = s;
    __syncthreads();
    if (c == 0) {
        float t = 0.f;
        #pragma unroll
        for (int j = 0; j < 8; j++) t += red[j];
        g_embsq[row] = t;
    }
}

__global__ void wsplit_kernel(const float* __restrict__ wq, const float* __restrict__ wk,
                              const float* __restrict__ wv, const float* __restrict__ wp) {
    int i = blockIdx.x*256 + threadIdx.x;
    int seg = i >> 16, j = i & 65535;
    const float* src = seg == 0 ? wq : seg == 1 ? wk : seg == 2 ? wv : wp;
    split16(src[j]*SWV, &g_wh[i], &g_wl[i]);
}

// 2048 blocks: (b,g) slab split into 32 chunks of 8192 floats
__global__ void __launch_bounds__(256) gn_partial(const float* __restrict__ z) {
    int blk = blockIdx.x;
    int bg = blk >> 5, chunk = blk & 31;
    const float4* p = (const float4*)(z + (size_t)bg*(16*THW) + (size_t)chunk*8192);
    double s = 0.0, s2 = 0.0;
    #pragma unroll
    for (int i = 0; i < 8; i++) {
        float4 v = p[threadIdx.x + i*256];
        s  += (double)v.x + (double)v.y + (double)v.z + (double)v.w;
        s2 += (double)v.x*v.x + (double)v.y*v.y + (double)v.z*v.z + (double)v.w*v.w;
    }
    __shared__ double ss[256], ss2[256];
    ss[threadIdx.x] = s; ss2[threadIdx.x] = s2;
    __syncthreads();
    for (int k = 128; k; k >>= 1) {
        if (threadIdx.x < k) { ss[threadIdx.x] += ss[threadIdx.x+k]; ss2[threadIdx.x] += ss2[threadIdx.x+k]; }
        __syncthreads();
    }
    if (threadIdx.x == 0) {
        atomicAdd(&g_sumd[bg], ss[0]);
        atomicAdd(&g_sumd[64 + bg], ss2[0]);
    }
}

__global__ void gn_final() {
    int bg = threadIdx.x;   // 64 threads
    double cnt = (double)(16*THW);
    double mu = g_sumd[bg]/cnt;
    double var = g_sumd[64+bg]/cnt - mu*mu;
    g_mu[bg] = (float)mu;
    g_rstd[bg] = rsqrtf((float)var + EPSV);
}

__global__ void transpose_norm_kernel(const float* __restrict__ z,
                                      const float* __restrict__ gamma,
                                      const float* __restrict__ beta) {
    __shared__ float tl[32][33];
    int b = blockIdx.z, c0 = blockIdx.y*32, s0 = blockIdx.x*32;
    int tx = threadIdx.x, ty = threadIdx.y;
    #pragma unroll
    for (int i = 0; i < 4; i++) {
        int c = c0 + ty + i*8;
        tl[ty + i*8][tx] = z[((size_t)(b*CC + c))*THW + s0 + tx];
    }
    __syncthreads();
    #pragma unroll
    for (int i = 0; i < 4; i++) {
        int th = s0 + ty + i*8;
        int c  = c0 + tx;
        float v = tl[tx][ty + i*8];
        size_t o = ((size_t)(b*THW + th))*CC + c;
        g_zp[o] = v;
        g_p2h[o] = __float2half_rn(v*SXV);
        int bg = b*GG + (c >> 4);
        float hn = (v - g_mu[bg]) * g_rstd[bg] * gamma[c] + beta[c];
        split16(hn*SXV, &g_p1h[o], &g_p1l[o]);
    }
}

// ================= HMMA GEMMs =================
// CTA tile 128x128, 8 warps (warp tile 32x64), K=256 chunked by 32, 2-stage cp.async.
// smem: 128 rows x 32 fp16, row pitch 80 bytes (conflict-free ldmatrix).

#define PITCH 80
#define TILE_B (128*PITCH)
#define STAGE3_B (4*TILE_B)
#define GSM3 (2*STAGE3_B)     // 81920
#define STAGE1_B (2*TILE_B)
#define GSM1 (2*STAGE1_B)     // 40960

__device__ __forceinline__ void g_load_stage3(
        uint32_t sb, int stage, int kc,
        const __half* Ah, const __half* Al,
        const __half* Bh, const __half* Bl,
        int row0, int col0, int tid) {
    int k0 = kc*32;
    uint32_t sbase = sb + stage*STAGE3_B;
    #pragma unroll
    for (int j = 0; j < 8; j++) {
        int idx = j*256 + tid;
        int t = idx >> 9;
        int r = (idx >> 2) & 127;
        int s = idx & 3;
        const __half* gsrc;
        if (t < 2) gsrc = (t ? Al : Ah) + (size_t)(row0 + r)*CC + k0 + s*8;
        else       gsrc = (t == 2 ? Bh : Bl) + (size_t)(col0 + r)*CC + k0 + s*8;
        uint32_t dst = sbase + t*TILE_B + r*PITCH + s*16;
        CP_ASYNC16(dst, gsrc);
    }
}

__global__ void __launch_bounds__(256)
gemm3fp16(const __half* __restrict__ Ah, const __half* __restrict__ Al,
          const __half* __restrict__ Bh, const __half* __restrict__ Bl,
          const float* __restrict__ colv, const float* __restrict__ rowv,
          float* __restrict__ Out, int out_ld, float alpha) {
    extern __shared__ char smem[];
    uint32_t sb = smem_u32(smem);
    int tid = threadIdx.x, wid = tid >> 5, lane = tid & 31;
    int row0 = blockIdx.y * 128, col0 = blockIdx.x * 128;
    int m_base = (wid & 3) * 32;
    int n_base = (wid >> 2) * 64;

    float acc[2][8][4];
    #pragma unroll
    for (int mt = 0; mt < 2; mt++)
        #pragma unroll
        for (int nt = 0; nt < 8; nt++)
            #pragma unroll
            for (int i = 0; i < 4; i++) acc[mt][nt][i] = 0.f;

    uint32_t a_roff = (uint32_t)(m_base + (lane & 15)) * PITCH + ((lane >> 4) * 16);
    uint32_t b_roff = (uint32_t)(n_base + ((lane >> 4) * 8) + (lane & 7)) * PITCH + (((lane >> 3) & 1) * 16);

    g_load_stage3(sb, 0, 0, Ah, Al, Bh, Bl, row0, col0, tid);
    CP_COMMIT();

    for (int kc = 0; kc < 8; kc++) {
        if (kc + 1 < 8) g_load_stage3(sb, (kc+1) & 1, kc+1, Ah, Al, Bh, Bl, row0, col0, tid);
        CP_COMMIT();
        CP_WAIT1();
        __syncthreads();
        uint32_t st = sb + (kc & 1)*STAGE3_B;
        #pragma unroll
        for (int ks = 0; ks < 2; ks++) {
            uint32_t koff = ks * 32;
            uint32_t ah[2][4], al[2][4], bh[8][2], bl[8][2];
            #pragma unroll
            for (int mt = 0; mt < 2; mt++) {
                uint32_t ad = st + a_roff + (uint32_t)mt*16*PITCH + koff;
                ldsm_x4(ah[mt], ad);
                ldsm_x4(al[mt], ad + TILE_B);
            }
            #pragma unroll
            for (int p = 0; p < 4; p++) {
                uint32_t r4[4];
                uint32_t bd = st + 2*TILE_B + b_roff + (uint32_t)p*16*PITCH + koff;
                ldsm_x4(r4, bd);
                bh[2*p][0] = r4[0]; bh[2*p][1] = r4[1];
                bh[2*p+1][0] = r4[2]; bh[2*p+1][1] = r4[3];
                ldsm_x4(r4, bd + TILE_B);
                bl[2*p][0] = r4[0]; bl[2*p][1] = r4[1];
                bl[2*p+1][0] = r4[2]; bl[2*p+1][1] = r4[3];
            }
            #pragma unroll
            for (int mt = 0; mt < 2; mt++)
                #pragma unroll
                for (int nt = 0; nt < 8; nt++) {
                    mma16816(acc[mt][nt], ah[mt], bh[nt]);
                    mma16816(acc[mt][nt], ah[mt], bl[nt]);
                    mma16816(acc[mt][nt], al[mt], bh[nt]);
                }
        }
        __syncthreads();
    }

    int g = lane >> 2, t4 = lane & 3;
    #pragma unroll
    for (int mt = 0; mt < 2; mt++) {
        int r_lo = row0 + m_base + mt*16 + g;
        int r_hi = r_lo + 8;
        float rv_lo = rowv ? rowv[r_lo] : 0.f;
        float rv_hi = rowv ? rowv[r_hi] : 0.f;
        #pragma unroll
        for (int nt = 0; nt < 8; nt++) {
            int c = col0 + n_base + nt*8 + 2*t4;
            float cv0 = colv[c], cv1 = colv[c+1];
            float2 vlo = make_float2(fmaf(alpha, acc[mt][nt][0], rv_lo + cv0),
                                     fmaf(alpha, acc[mt][nt][1], rv_lo + cv1));
            float2 vhi = make_float2(fmaf(alpha, acc[mt][nt][2], rv_hi + cv0),
                                     fmaf(alpha, acc[mt][nt][3], rv_hi + cv1));
            *(float2*)(Out + (size_t)r_lo*out_ld + c) = vlo;
            *(float2*)(Out + (size_t)r_hi*out_ld + c) = vhi;
        }
    }
}

// single-pass (hi only) GEMM for distance matrices
__device__ __forceinline__ void g_load_stage1(
        uint32_t sb, int stage, int kc,
        const __half* Ah, const __half* Bh,
        int row0, int col0, int tid) {
    int k0 = kc*32;
    uint32_t sbase = sb + stage*STAGE1_B;
    #pragma unroll
    for (int j = 0; j < 4; j++) {
        int idx = j*256 + tid;      // 0..1023
        int t = idx >> 9;           // 0=A, 1=B
        int r = (idx >> 2) & 127;
        int s = idx & 3;
        const __half* gsrc = (t ? Bh + (size_t)(col0 + r)*CC : Ah + (size_t)(row0 + r)*CC) + k0 + s*8;
        uint32_t dst = sbase + t*TILE_B + r*PITCH + s*16;
        CP_ASYNC16(dst, gsrc);
    }
}

__global__ void __launch_bounds__(256)
gemm1fp16(const __half* __restrict__ Ah, const __half* __restrict__ Bh,
          const float* __restrict__ colv, const float* __restrict__ rowv,
          float* __restrict__ Out, int out_ld, float alpha) {
    extern __shared__ char smem[];
    uint32_t sb = smem_u32(smem);
    int tid = threadIdx.x, wid = tid >> 5, lane = tid & 31;
    int row0 = blockIdx.y * 128, col0 = blockIdx.x * 128;
    int m_base = (wid & 3) * 32;
    int n_base = (wid >> 2) * 64;

    float acc[2][8][4];
    #pragma unroll
    for (int mt = 0; mt < 2; mt++)
        #pragma unroll
        for (int nt = 0; nt < 8; nt++)
            #pragma unroll
            for (int i = 0; i < 4; i++) acc[mt][nt][i] = 0.f;

    uint32_t a_roff = (uint32_t)(m_base + (lane & 15)) * PITCH + ((lane >> 4) * 16);
    uint32_t b_roff = (uint32_t)(n_base + ((lane >> 4) * 8) + (lane & 7)) * PITCH + (((lane >> 3) & 1) * 16);

    g_load_stage1(sb, 0, 0, Ah, Bh, row0, col0, tid);
    CP_COMMIT();

    for (int kc = 0; kc < 8; kc++) {
        if (kc + 1 < 8) g_load_stage1(sb, (kc+1) & 1, kc+1, Ah, Bh, row0, col0, tid);
        CP_COMMIT();
        CP_WAIT1();
        __syncthreads();
        uint32_t st = sb + (kc & 1)*STAGE1_B;
        #pragma unroll
        for (int ks = 0; ks < 2; ks++) {
            uint32_t koff = ks * 32;
            uint32_t ah[2][4], bh[8][2];
            #pragma unroll
            for (int mt = 0; mt < 2; mt++)
                ldsm_x4(ah[mt], st + a_roff + (uint32_t)mt*16*PITCH + koff);
            #pragma unroll
            for (int p = 0; p < 4; p++) {
                uint32_t r4[4];
                ldsm_x4(r4, st + TILE_B + b_roff + (uint32_t)p*16*PITCH + koff);
                bh[2*p][0] = r4[0]; bh[2*p][1] = r4[1];
                bh[2*p+1][0] = r4[2]; bh[2*p+1][1] = r4[3];
            }
            #pragma unroll
            for (int mt = 0; mt < 2; mt++)
                #pragma unroll
                for (int nt = 0; nt < 8; nt++)
                    mma16816(acc[mt][nt], ah[mt], bh[nt]);
        }
        __syncthreads();
    }

    int g = lane >> 2, t4 = lane & 3;
    #pragma unroll
    for (int mt = 0; mt < 2; mt++) {
        int r_lo = row0 + m_base + mt*16 + g;
        int r_hi = r_lo + 8;
        float rv_lo = rowv[r_lo];
        float rv_hi = rowv[r_hi];
        #pragma unroll
        for (int nt = 0; nt < 8; nt++) {
            int c = col0 + n_base + nt*8 + 2*t4;
            float cv0 = colv[c], cv1 = colv[c+1];
            float2 vlo = make_float2(fmaf(alpha, acc[mt][nt][0], rv_lo + cv0),
                                     fmaf(alpha, acc[mt][nt][1], rv_lo + cv1));
            float2 vhi = make_float2(fmaf(alpha, acc[mt][nt][2], rv_hi + cv0),
                                     fmaf(alpha, acc[mt][nt][3], rv_hi + cv1));
            *(float2*)(Out + (size_t)r_lo*out_ld + c) = vlo;
            *(float2*)(Out + (size_t)r_hi*out_ld + c) = vhi;
        }
    }
}

// ================= attention =================
__global__ void __launch_bounds__(256) attn_kernel() {
    __shared__ float qs[16][256], ks[16][256];
    __shared__ float att[16][16];
    int x = blockIdx.x;
    int b = x >> 10;
    int s = x & (HWp - 1);
    size_t base = ((size_t)(b*TT)*HWp + s)*CC;
    const size_t tstr = (size_t)HWp*CC;
    int tid = threadIdx.x;
    for (int e = tid; e < 16*256; e += 256) {
        int t = e >> 8, c = e & 255;
        qs[t][c] = g_q[base + (size_t)t*tstr + c];
        ks[t][c] = g_k[base + (size_t)t*tstr + c];
    }
    __syncthreads();
    int i = tid >> 4, j = tid & 15;
    float acc = 0.f;
    #pragma unroll 8
    for (int c = 0; c < 256; c++) acc += qs[i][c]*ks[j][c];
    att[i][j] = acc * 0.0625f;
    __syncthreads();
    if (tid < 16) {
        float m = -3.4e38f;
        for (int jj = 0; jj < 16; jj++) m = fmaxf(m, att[tid][jj]);
        float ssum = 0.f;
        for (int jj = 0; jj < 16; jj++) { float e = expf(att[tid][jj]-m); att[tid][jj] = e; ssum += e; }
        float r = 1.0f/ssum;
        for (int jj = 0; jj < 16; jj++) att[tid][jj] *= r;
    }
    __syncthreads();
    int c = tid;
    float vv[16];
    #pragma unroll
    for (int tk = 0; tk < 16; tk++) vv[tk] = g_v[base + (size_t)tk*tstr + c];
    #pragma unroll
    for (int tq = 0; tq < 16; tq++) {
        float o = 0.f;
        #pragma unroll
        for (int tk = 0; tk < 16; tk++) o += att[tq][tk]*vv[tk];
        size_t oi = base + (size_t)tq*tstr + c;
        split16(o*SXV, &g_p1h[oi], &g_p1l[oi]);
    }
}

// ztf = zt + diff; keep fp32 in g_q (refinement), write hi-only split, xsq branch1
__global__ void add_diff_kernel() {
    int p = blockIdx.x, c = threadIdx.x;
    size_t idx = (size_t)p*CC + c;
    int t = (p / HWp) % TT;
    float d = 0.f;
    if (t > 0) d = g_zp[idx] - g_zp[idx - (size_t)HWp*CC];
    float v = g_q[idx] + d;
    g_q[idx] = v;
    g_p1h[idx] = __float2half_rn(v*SXV);
    float s = v*v;
    #pragma unroll
    for (int o = 16; o; o >>= 1) s += __shfl_xor_sync(0xffffffffu, s, o);
    __shared__ float red[8];
    if ((c & 31) == 0) red[c >> 5] = s;
    __syncthreads();
    if (c == 0) {
        float tt = 0.f;
        #pragma unroll
        for (int j = 0; j < 8; j++) tt += red[j];
        g_xsq[NN + p] = tt;
    }
}

__global__ void rowsq_kernel(const float* __restrict__ X) {
    int warp = threadIdx.x >> 5, lane = threadIdx.x & 31;
    int row = blockIdx.x*8 + warp;
    const float* r = X + (size_t)row*CC;
    float s = 0.f;
    for (int c = lane; c < CC; c += 32) s += r[c]*r[c];
    #pragma unroll
    for (int o = 16; o; o >>= 1) s += __shfl_down_sync(0xffffffffu, s, o);
    if (!lane) g_xsq[row] = s;
}

// warp-per-row: argmin (top-2 + fp32 refinement) + 1/d rownorm + column accumulation
__global__ void __launch_bounds__(256) vq_reduce_kernel(int branch, const float* __restrict__ X,
                                                        const float* __restrict__ EMB) {
    __shared__ float sacc[1024];
    int tid = threadIdx.x, w = tid >> 5, lane = tid & 31;
    for (int i = tid; i < 1024; i += 256) sacc[i] = 0.f;
    __syncthreads();
    int row0 = blockIdx.x * 64;
    float acc[32];
    #pragma unroll
    for (int j = 0; j < 32; j++) acc[j] = 0.f;
    for (int rr = 0; rr < 8; rr++) {
        int row = row0 + w*8 + rr;
        const float* dr = g_dist + (size_t)row*KCB;
        float inv[32];
        float lsum = 0.f, m1 = 3.4e38f, m2 = 3.4e38f; int i1 = 0;
        #pragma unroll
        for (int j = 0; j < 32; j++) {
            float d = dr[j*32 + lane];
            float iv = 1.0f/d;
            inv[j] = iv; lsum += iv;
            if (d < m1) { m2 = m1; m1 = d; i1 = j*32 + lane; }
            else if (d < m2) m2 = d;
        }
        #pragma unroll
        for (int o = 16; o; o >>= 1) {
            lsum += __shfl_xor_sync(0xffffffffu, lsum, o);
            float o1 = __shfl_xor_sync(0xffffffffu, m1, o);
            int   oi = __shfl_xor_sync(0xffffffffu, i1, o);
            float o2 = __shfl_xor_sync(0xffffffffu, m2, o);
            if (o1 < m1 || (o1 == m1 && oi < i1)) { m2 = fminf(m1, o2); m1 = o1; i1 = oi; }
            else m2 = fminf(m2, o1);
        }
        int idxf = i1;
        if (m2 - m1 <= REFINE_TH) {
            float xr[8];
            #pragma unroll
            for (int k = 0; k < 8; k++) xr[k] = X[(size_t)row*CC + lane + 32*k];
            float sA = g_xsq[branch*NN + row];
            float thr = m1 + REFINE_TH;
            float bestd = 3.4e38f; int besti = 0;
            for (int j = 0; j < 32; j++) {
                float d = dr[j*32 + lane];
                unsigned bal = __ballot_sync(0xffffffffu, d <= thr);
                while (bal) {
                    int src = __ffs(bal) - 1; bal &= bal - 1;
                    int cidx = j*32 + src;
                    const float* er = EMB + (size_t)cidx*CC;
                    float dot = 0.f;
                    #pragma unroll
                    for (int k = 0; k < 8; k++) dot = fmaf(xr[k], er[lane + 32*k], dot);
                    #pragma unroll
                    for (int o = 16; o; o >>= 1) dot += __shfl_xor_sync(0xffffffffu, dot, o);
                    float de = fmaf(-2.f, dot, sA + g_embsq[branch*KCB + cidx]);
                    if (de < bestd) { bestd = de; besti = cidx; }
                }
            }
            idxf = besti;
        }
        if (lane == 0) {
            g_idx[branch*NN + row] = idxf;
            atomicAdd(&g_hist[branch*KCB + idxf], 1);
        }
        float irs = 1.0f/lsum;
        #pragma unroll
        for (int j = 0; j < 32; j++) acc[j] += inv[j]*irs;
    }
    #pragma unroll
    for (int j = 0; j < 32; j++) atomicAdd(&sacc[j*32 + lane], acc[j]);
    __syncthreads();
    for (int i = tid; i < 1024; i += 256) atomicAdd(&g_avg[branch*KCB + i], sacc[i]);
}

__global__ void assemble_kernel(const float* __restrict__ emb_s,
                                const float* __restrict__ emb_t,
                                float* __restrict__ out) {
    __shared__ float tl[32][33];
    __shared__ float mred[256];
    int b = blockIdx.z, c0 = blockIdx.y*32, s0 = blockIdx.x*32;
    int tx = threadIdx.x, ty = threadIdx.y;
    float lm = 0.f;
    #pragma unroll
    for (int i = 0; i < 4; i++) {
        int th = s0 + ty + i*8;
        int p = b*THW + th;
        int is = g_idx[p], it = g_idx[NN + p];
        int c = c0 + tx;
        float zpv = g_zp[(size_t)p*CC + c];
        float zq  = emb_t[(size_t)it*CC + c] + emb_s[(size_t)is*CC + c];
        float d = zq - zpv;
        lm += d*d;
        tl[ty + i*8][tx] = zpv + d;
    }
    int tid = ty*32 + tx;
    mred[tid] = lm;
    __syncthreads();
    for (int s = 128; s; s >>= 1) { if (tid < s) mred[tid] += mred[tid+s]; __syncthreads(); }
    if (tid == 0) atomicAdd(&g_mse, (double)mred[0]);
    #pragma unroll
    for (int i = 0; i < 4; i++) {
        int c  = c0 + ty + i*8;
        int th = s0 + tx;
        out[((size_t)(b*CC + c))*THW + th] = tl[tx][ty + i*8];
    }
}

__global__ void ind_write_kernel(float* __restrict__ out) {
    int gid = blockIdx.x*256 + threadIdx.x;
    int br = gid >> 16;
    int o  = gid & (NN - 1);
    int b = o / (TT*HWp);
    int rem = o - b*(TT*HWp);
    int t = rem / HWp;
    int s = rem & (HWp - 1);
    int src = (t*BB + b)*HWp + s;
    out[(br ? OFF_INDT : OFF_INDS) + o] = (float)g_idx[br*NN + src];
}

__global__ void __launch_bounds__(1024) finalize_kernel(float* __restrict__ out) {
    __shared__ double sd[1024];
    int t = threadIdx.x;
    if (t == 0) out[OFF_LOSS] = (float)(1.25 * g_mse / ((double)NN * (double)CC));
    for (int br = 0; br < 2; br++) {
        double e = (double)g_hist[br*KCB + t] / (double)NN;
        sd[t] = e * log(e + 1e-10);
        __syncthreads();
        for (int s = 512; s; s >>= 1) { if (t < s) sd[t] += sd[t+s]; __syncthreads(); }
        if (t == 0) out[br == 0 ? OFF_PERPS : OFF_PERPT] = (float)exp(-sd[0]);
        __syncthreads();
    }
    double kl[2];
    for (int br = 0; br < 2; br++) {
        double a = (double)g_avg[br*KCB + t] / (double)NN;
        sd[t] = a; __syncthreads();
        for (int s = 512; s; s >>= 1) { if (t < s) sd[t] = fmax(sd[t], sd[t+s]); __syncthreads(); }
        double m = sd[0]; __syncthreads();
        sd[t] = exp(a - m); __syncthreads();
        for (int s = 512; s; s >>= 1) { if (t < s) sd[t] += sd[t+s]; __syncthreads(); }
        double Z = sd[0]; __syncthreads();
        sd[t] = a; __syncthreads();
        for (int s = 512; s; s >>= 1) { if (t < s) sd[t] += sd[t+s]; __syncthreads(); }
        double SA = sd[0]; __syncthreads();
        double lse = m + log(Z);
        double tgt = 1.0 / (double)KCB;
        kl[br] = tgt * (log(tgt) + lse - SA / (double)KCB);
    }
    if (t == 0) out[OFF_LOSS2] = (float)(0.1 * (kl[0] + kl[1]));
}

// ================= host =================

extern "C" void kernel_launch(void* const* d_in, const int* in_sizes, int n_in,
                              void* d_out, int out_size) {
    (void)in_sizes; (void)n_in; (void)out_size;
    const float* z     = (const float*)d_in[0];
    const float* emb_s = (const float*)d_in[1];
    const float* emb_t = (const float*)d_in[2];
    const float* gamma = (const float*)d_in[3];
    const float* beta  = (const float*)d_in[4];
    const float* wq = (const float*)d_in[5];
    const float* bq = (const float*)d_in[6];
    const float* wk = (const float*)d_in[7];
    const float* bk = (const float*)d_in[8];
    const float* wv = (const float*)d_in[9];
    const float* bv = (const float*)d_in[10];
    const float* wp = (const float*)d_in[11];
    const float* bp = (const float*)d_in[12];
    float* out = (float*)d_out;

    float *p_zp, *p_q, *p_k, *p_v, *p_dist, *p_embsq, *p_xsq;
    __half *p1h, *p1l, *p2h, *pwh, *pwl, *pebh;
    cudaGetSymbolAddress((void**)&p_zp, g_zp);
    cudaGetSymbolAddress((void**)&p_q,  g_q);
    cudaGetSymbolAddress((void**)&p_k,  g_k);
    cudaGetSymbolAddress((void**)&p_v,  g_v);
    cudaGetSymbolAddress((void**)&p_dist, g_dist);
    cudaGetSymbolAddress((void**)&p_embsq, g_embsq);
    cudaGetSymbolAddress((void**)&p_xsq, g_xsq);
    cudaGetSymbolAddress((void**)&p1h, g_p1h);
    cudaGetSymbolAddress((void**)&p1l, g_p1l);
    cudaGetSymbolAddress((void**)&p2h, g_p2h);
    cudaGetSymbolAddress((void**)&pwh, g_wh);
    cudaGetSymbolAddress((void**)&pwl, g_wl);
    cudaGetSymbolAddress((void**)&pebh, g_ebh);

    cudaFuncSetAttribute(gemm3fp16, cudaFuncAttributeMaxDynamicSharedMemorySize, GSM3);
    cudaFuncSetAttribute(gemm1fp16, cudaFuncAttributeMaxDynamicSharedMemorySize, GSM1);

    zero_kernel<<<8, 256>>>();
    embsplit_kernel<<<2*KCB, 256>>>(emb_s, emb_t);
    wsplit_kernel<<<4*CC*CC/256, 256>>>(wq, wk, wv, wp);
    gn_partial<<<2048, 256>>>(z);
    gn_final<<<1, 64>>>();
    transpose_norm_kernel<<<dim3(THW/32, CC/32, BB), dim3(32, 8)>>>(z, gamma, beta);
    rowsq_kernel<<<NN/8, 256>>>(p_zp);

    // q, k, v convs (3-pass fp16x2-split GEMM)
    gemm3fp16<<<dim3(CC/128, NN/128), 256, GSM3>>>(p1h, p1l, pwh,           pwl,           bq, nullptr, p_q, CC, ALPHA_CONV);
    gemm3fp16<<<dim3(CC/128, NN/128), 256, GSM3>>>(p1h, p1l, pwh + CC*CC,   pwl + CC*CC,   bk, nullptr, p_k, CC, ALPHA_CONV);
    gemm3fp16<<<dim3(CC/128, NN/128), 256, GSM3>>>(p1h, p1l, pwh + 2*CC*CC, pwl + 2*CC*CC, bv, nullptr, p_v, CC, ALPHA_CONV);

    attn_kernel<<<BB*HWp, 256>>>();
    gemm3fp16<<<dim3(CC/128, NN/128), 256, GSM3>>>(p1h, p1l, pwh + 3*CC*CC, pwl + 3*CC*CC, bp, nullptr, p_q, CC, ALPHA_CONV);
    add_diff_kernel<<<NN, 256>>>();

    // spatial VQ (single-pass dist GEMM; near-ties refined in fp32)
    gemm1fp16<<<dim3(KCB/128, NN/128), 256, GSM1>>>(p2h, pebh, p_embsq, p_xsq, p_dist, KCB, ALPHA_DIST);
    vq_reduce_kernel<<<NN/64, 256>>>(0, p_zp, emb_s);

    // temporal VQ
    gemm1fp16<<<dim3(KCB/128, NN/128), 256, GSM1>>>(p1h, pebh + (size_t)KCB*CC, p_embsq + KCB, p_xsq + NN, p_dist, KCB, ALPHA_DIST);
    vq_reduce_kernel<<<NN/64, 256>>>(1, p_q, emb_t);

    assemble_kernel<<<dim3(THW/32, CC/32, BB), dim3(32, 8)>>>(emb_s, emb_t, out);
    ind_write_kernel<<<2*NN/256, 256>>>(out);
    finalize_kernel<<<1, 1024>>>(out);
}

// round 7
// speedup vs baseline: 3.7467x; 1.9578x over previous
#include <cuda_runtime.h>
#include <cuda_fp16.h>
#include <math.h>
#include <cstdint>

#define BB 4
#define CC 256
#define TT 16
#define HH 32
#define WW 32
#define KCB 1024
#define GG 16
#define HWp (HH*WW)          // 1024
#define THW (TT*HWp)         // 16384
#define NN (BB*THW)          // 65536
#define EPSV 1e-6f

#define SXV 64.0f
#define SWV 64.0f
#define SEV 16384.0f
#define ALPHA_CONV (1.0f/(64.0f*64.0f))
#define ALPHA_DIST (-2.0f/(64.0f*16384.0f))
#define REFINE_TH 2e-4f

// ---- output layout ----
#define SZ_ZQ     (BB*CC*THW)
#define OFF_LOSS  (SZ_ZQ)
#define OFF_LOSS2 (SZ_ZQ+1)
#define OFF_INDS  (SZ_ZQ+2)
#define OFF_INDT  (OFF_INDS+NN)
#define OFF_PERPS (OFF_INDT+NN)
#define OFF_PERPT (OFF_PERPS+1)

// ---- scratch ----
__device__ float g_zp[NN*CC];
__device__ float g_q [NN*CC];
__device__ float g_k [NN*CC];
__device__ float g_v [NN*CC];
__device__ float g_dist[NN*KCB];     // mixed: even 32-col blocks hold 1/d, odd hold d
__device__ __half g_p1h[NN*CC];
__device__ __half g_p1l[NN*CC];
__device__ __half g_p2h[NN*CC];
__device__ __half g_wh[4*CC*CC];
__device__ __half g_wl[4*CC*CC];
__device__ __half g_ebh[2*KCB*CC];
__device__ float g_xsq[2*NN];
__device__ float g_embsq[2*KCB];
__device__ float g_mu[BB*GG];
__device__ float g_rstd[BB*GG];
__device__ double g_sumd[2*BB*GG];
__device__ int   g_idx[2*NN];
__device__ float g_avg[2*KCB];
__device__ int   g_hist[2*KCB];
__device__ double g_mse;

// ================= helpers =================
__device__ __forceinline__ uint32_t smem_u32(const void* p) {
    uint32_t a;
    asm("{ .reg .u64 t; cvta.to.shared.u64 t, %1; cvt.u32.u64 %0, t; }" : "=r"(a) : "l"(p));
    return a;
}
__device__ __forceinline__ float rcp_approx(float x) {
    float r;
    asm("rcp.approx.ftz.f32 %0, %1;" : "=f"(r) : "f"(x));
    return r;
}
#define CP_ASYNC16(dst, src) \
    asm volatile("cp.async.cg.shared.global [%0], [%1], 16;" :: "r"(dst), "l"(src))
#define CP_COMMIT() asm volatile("cp.async.commit_group;" ::: "memory")
#define CP_WAIT1()  asm volatile("cp.async.wait_group 1;" ::: "memory")

__device__ __forceinline__ void ldsm_x4(uint32_t* r, uint32_t addr) {
    asm volatile("ldmatrix.sync.aligned.m8n8.x4.shared.b16 {%0,%1,%2,%3}, [%4];"
        : "=r"(r[0]), "=r"(r[1]), "=r"(r[2]), "=r"(r[3]) : "r"(addr));
}
__device__ __forceinline__ void mma16816(float* d, const uint32_t* a, const uint32_t* b) {
    asm volatile("mma.sync.aligned.m16n8k16.row.col.f32.f16.f16.f32 "
        "{%0,%1,%2,%3}, {%4,%5,%6,%7}, {%8,%9}, {%0,%1,%2,%3};"
        : "+f"(d[0]), "+f"(d[1]), "+f"(d[2]), "+f"(d[3])
        : "r"(a[0]), "r"(a[1]), "r"(a[2]), "r"(a[3]), "r"(b[0]), "r"(b[1]));
}
__device__ __forceinline__ void split16(float v, __half* hp, __half* lp) {
    __half h = __float2half_rn(v);
    *hp = h;
    *lp = __float2half_rn(v - __half2float(h));
}

// ================= small kernels =================

__global__ void zero_kernel() {
    int i = blockIdx.x*256 + threadIdx.x;
    if (i < 2*KCB) { g_avg[i] = 0.f; g_hist[i] = 0; }
    if (i < 2*BB*GG) g_sumd[i] = 0.0;
    if (i == 0) g_mse = 0.0;
}

__global__ void embsplit_kernel(const float* __restrict__ es, const float* __restrict__ et) {
    int row = blockIdx.x, c = threadIdx.x;
    const float* src = (row < KCB) ? (es + (size_t)row*CC) : (et + (size_t)(row-KCB)*CC);
    float v = src[c];
    g_ebh[(size_t)row*CC + c] = __float2half_rn(v*SEV);
    float s = v*v;
    #pragma unroll
    for (int off = 16; off; off >>= 1) s += __shfl_xor_sync(0xffffffffu, s, off);
    __shared__ float red[8];
    if ((c & 31) == 0) red[c >> 5] = s;
    __syncthreads();
    if (c == 0) {
        float t = 0.f;
        #pragma unroll
        for (int j = 0; j < 8; j++) t += red[j];
        g_embsq[row] = t;
    }
}

__global__ void wsplit_kernel(const float* __restrict__ wq, const float* __restrict__ wk,
                              const float* __restrict__ wv, const float* __restrict__ wp) {
    int i = blockIdx.x*256 + threadIdx.x;
    int seg = i >> 16, j = i & 65535;
    const float* src = seg == 0 ? wq : seg == 1 ? wk : seg == 2 ? wv : wp;
    split16(src[j]*SWV, &g_wh[i], &g_wl[i]);
}

// fp32 accumulation (FP64 pipe was the R6 bottleneck); double only at final atomics
__global__ void __launch_bounds__(256) gn_partial(const float* __restrict__ z) {
    int blk = blockIdx.x;
    int bg = blk >> 5, chunk = blk & 31;
    const float4* p = (const float4*)(z + (size_t)bg*(16*THW) + (size_t)chunk*8192);
    float s = 0.f, s2 = 0.f;
    #pragma unroll
    for (int i = 0; i < 8; i++) {
        float4 v = p[threadIdx.x + i*256];
        s  += v.x + v.y + v.z + v.w;
        s2 += v.x*v.x + v.y*v.y + v.z*v.z + v.w*v.w;
    }
    __shared__ float ss[256], ss2[256];
    ss[threadIdx.x] = s; ss2[threadIdx.x] = s2;
    __syncthreads();
    for (int k = 128; k; k >>= 1) {
        if (threadIdx.x < k) { ss[threadIdx.x] += ss[threadIdx.x+k]; ss2[threadIdx.x] += ss2[threadIdx.x+k]; }
        __syncthreads();
    }
    if (threadIdx.x == 0) {
        atomicAdd(&g_sumd[bg], (double)ss[0]);
        atomicAdd(&g_sumd[64 + bg], (double)ss2[0]);
    }
}

__global__ void gn_final() {
    int bg = threadIdx.x;
    double cnt = (double)(16*THW);
    double mu = g_sumd[bg]/cnt;
    double var = g_sumd[64+bg]/cnt - mu*mu;
    g_mu[bg] = (float)mu;
    g_rstd[bg] = rsqrtf((float)var + EPSV);
}

__global__ void transpose_norm_kernel(const float* __restrict__ z,
                                      const float* __restrict__ gamma,
                                      const float* __restrict__ beta) {
    __shared__ float tl[32][33];
    int b = blockIdx.z, c0 = blockIdx.y*32, s0 = blockIdx.x*32;
    int tx = threadIdx.x, ty = threadIdx.y;
    #pragma unroll
    for (int i = 0; i < 4; i++) {
        int c = c0 + ty + i*8;
        tl[ty + i*8][tx] = z[((size_t)(b*CC + c))*THW + s0 + tx];
    }
    __syncthreads();
    #pragma unroll
    for (int i = 0; i < 4; i++) {
        int th = s0 + ty + i*8;
        int c  = c0 + tx;
        float v = tl[tx][ty + i*8];
        size_t o = ((size_t)(b*THW + th))*CC + c;
        g_zp[o] = v;
        g_p2h[o] = __float2half_rn(v*SXV);
        int bg = b*GG + (c >> 4);
        float hn = (v - g_mu[bg]) * g_rstd[bg] * gamma[c] + beta[c];
        split16(hn*SXV, &g_p1h[o], &g_p1l[o]);
    }
}

// ================= HMMA GEMMs =================
#define PITCH 80
#define TILE_B (128*PITCH)
#define STAGE3_B (4*TILE_B)
#define GSM3 (2*STAGE3_B)     // 81920
#define STAGE1_B (2*TILE_B)
#define GSM1 (2*STAGE1_B)     // 40960

__device__ __forceinline__ void g_load_stage3(
        uint32_t sb, int stage, int kc,
        const __half* Ah, const __half* Al,
        const __half* Bh, const __half* Bl,
        int row0, int col0, int tid) {
    int k0 = kc*32;
    uint32_t sbase = sb + stage*STAGE3_B;
    #pragma unroll
    for (int j = 0; j < 8; j++) {
        int idx = j*256 + tid;
        int t = idx >> 9;
        int r = (idx >> 2) & 127;
        int s = idx & 3;
        const __half* gsrc;
        if (t < 2) gsrc = (t ? Al : Ah) + (size_t)(row0 + r)*CC + k0 + s*8;
        else       gsrc = (t == 2 ? Bh : Bl) + (size_t)(col0 + r)*CC + k0 + s*8;
        uint32_t dst = sbase + t*TILE_B + r*PITCH + s*16;
        CP_ASYNC16(dst, gsrc);
    }
}

__global__ void __launch_bounds__(256)
gemm3fp16(const __half* __restrict__ Ah, const __half* __restrict__ Al,
          const __half* __restrict__ Bh, const __half* __restrict__ Bl,
          const float* __restrict__ colv,
          float* __restrict__ Out, int out_ld, float alpha) {
    extern __shared__ char smem[];
    uint32_t sb = smem_u32(smem);
    int tid = threadIdx.x, wid = tid >> 5, lane = tid & 31;
    int row0 = blockIdx.y * 128, col0 = blockIdx.x * 128;
    int m_base = (wid & 3) * 32;
    int n_base = (wid >> 2) * 64;

    float acc[2][8][4];
    #pragma unroll
    for (int mt = 0; mt < 2; mt++)
        #pragma unroll
        for (int nt = 0; nt < 8; nt++)
            #pragma unroll
            for (int i = 0; i < 4; i++) acc[mt][nt][i] = 0.f;

    uint32_t a_roff = (uint32_t)(m_base + (lane & 15)) * PITCH + ((lane >> 4) * 16);
    uint32_t b_roff = (uint32_t)(n_base + ((lane >> 4) * 8) + (lane & 7)) * PITCH + (((lane >> 3) & 1) * 16);

    g_load_stage3(sb, 0, 0, Ah, Al, Bh, Bl, row0, col0, tid);
    CP_COMMIT();

    for (int kc = 0; kc < 8; kc++) {
        if (kc + 1 < 8) g_load_stage3(sb, (kc+1) & 1, kc+1, Ah, Al, Bh, Bl, row0, col0, tid);
        CP_COMMIT();
        CP_WAIT1();
        __syncthreads();
        uint32_t st = sb + (kc & 1)*STAGE3_B;
        #pragma unroll
        for (int ks = 0; ks < 2; ks++) {
            uint32_t koff = ks * 32;
            uint32_t ah[2][4], al[2][4], bh[8][2], bl[8][2];
            #pragma unroll
            for (int mt = 0; mt < 2; mt++) {
                uint32_t ad = st + a_roff + (uint32_t)mt*16*PITCH + koff;
                ldsm_x4(ah[mt], ad);
                ldsm_x4(al[mt], ad + TILE_B);
            }
            #pragma unroll
            for (int p = 0; p < 4; p++) {
                uint32_t r4[4];
                uint32_t bd = st + 2*TILE_B + b_roff + (uint32_t)p*16*PITCH + koff;
                ldsm_x4(r4, bd);
                bh[2*p][0] = r4[0]; bh[2*p][1] = r4[1];
                bh[2*p+1][0] = r4[2]; bh[2*p+1][1] = r4[3];
                ldsm_x4(r4, bd + TILE_B);
                bl[2*p][0] = r4[0]; bl[2*p][1] = r4[1];
                bl[2*p+1][0] = r4[2]; bl[2*p+1][1] = r4[3];
            }
            #pragma unroll
            for (int mt = 0; mt < 2; mt++)
                #pragma unroll
                for (int nt = 0; nt < 8; nt++) {
                    mma16816(acc[mt][nt], ah[mt], bh[nt]);
                    mma16816(acc[mt][nt], ah[mt], bl[nt]);
                    mma16816(acc[mt][nt], al[mt], bh[nt]);
                }
        }
        __syncthreads();
    }

    int g = lane >> 2, t4 = lane & 3;
    #pragma unroll
    for (int mt = 0; mt < 2; mt++) {
        int r_lo = row0 + m_base + mt*16 + g;
        int r_hi = r_lo + 8;
        #pragma unroll
        for (int nt = 0; nt < 8; nt++) {
            int c = col0 + n_base + nt*8 + 2*t4;
            float cv0 = colv[c], cv1 = colv[c+1];
            float2 vlo = make_float2(fmaf(alpha, acc[mt][nt][0], cv0),
                                     fmaf(alpha, acc[mt][nt][1], cv1));
            float2 vhi = make_float2(fmaf(alpha, acc[mt][nt][2], cv0),
                                     fmaf(alpha, acc[mt][nt][3], cv1));
            *(float2*)(Out + (size_t)r_lo*out_ld + c) = vlo;
            *(float2*)(Out + (size_t)r_hi*out_ld + c) = vhi;
        }
    }
}

// single-pass dist GEMM; epilogue stores iv=1/d for even 32-col blocks (nt<4), d for odd
__device__ __forceinline__ void g_load_stage1(
        uint32_t sb, int stage, int kc,
        const __half* Ah, const __half* Bh,
        int row0, int col0, int tid) {
    int k0 = kc*32;
    uint32_t sbase = sb + stage*STAGE1_B;
    #pragma unroll
    for (int j = 0; j < 4; j++) {
        int idx = j*256 + tid;
        int t = idx >> 9;
        int r = (idx >> 2) & 127;
        int s = idx & 3;
        const __half* gsrc = (t ? Bh + (size_t)(col0 + r)*CC : Ah + (size_t)(row0 + r)*CC) + k0 + s*8;
        uint32_t dst = sbase + t*TILE_B + r*PITCH + s*16;
        CP_ASYNC16(dst, gsrc);
    }
}

__global__ void __launch_bounds__(256)
gemm_dist(const __half* __restrict__ Ah, const __half* __restrict__ Bh,
          const float* __restrict__ colv, const float* __restrict__ rowv,
          float* __restrict__ Out, int out_ld, float alpha) {
    extern __shared__ char smem[];
    uint32_t sb = smem_u32(smem);
    int tid = threadIdx.x, wid = tid >> 5, lane = tid & 31;
    int row0 = blockIdx.y * 128, col0 = blockIdx.x * 128;
    int m_base = (wid & 3) * 32;
    int n_base = (wid >> 2) * 64;

    float acc[2][8][4];
    #pragma unroll
    for (int mt = 0; mt < 2; mt++)
        #pragma unroll
        for (int nt = 0; nt < 8; nt++)
            #pragma unroll
            for (int i = 0; i < 4; i++) acc[mt][nt][i] = 0.f;

    uint32_t a_roff = (uint32_t)(m_base + (lane & 15)) * PITCH + ((lane >> 4) * 16);
    uint32_t b_roff = (uint32_t)(n_base + ((lane >> 4) * 8) + (lane & 7)) * PITCH + (((lane >> 3) & 1) * 16);

    g_load_stage1(sb, 0, 0, Ah, Bh, row0, col0, tid);
    CP_COMMIT();

    for (int kc = 0; kc < 8; kc++) {
        if (kc + 1 < 8) g_load_stage1(sb, (kc+1) & 1, kc+1, Ah, Bh, row0, col0, tid);
        CP_COMMIT();
        CP_WAIT1();
        __syncthreads();
        uint32_t st = sb + (kc & 1)*STAGE1_B;
        #pragma unroll
        for (int ks = 0; ks < 2; ks++) {
            uint32_t koff = ks * 32;
            uint32_t ah[2][4], bh[8][2];
            #pragma unroll
            for (int mt = 0; mt < 2; mt++)
                ldsm_x4(ah[mt], st + a_roff + (uint32_t)mt*16*PITCH + koff);
            #pragma unroll
            for (int p = 0; p < 4; p++) {
                uint32_t r4[4];
                ldsm_x4(r4, st + TILE_B + b_roff + (uint32_t)p*16*PITCH + koff);
                bh[2*p][0] = r4[0]; bh[2*p][1] = r4[1];
                bh[2*p+1][0] = r4[2]; bh[2*p+1][1] = r4[3];
            }
            #pragma unroll
            for (int mt = 0; mt < 2; mt++)
                #pragma unroll
                for (int nt = 0; nt < 8; nt++)
                    mma16816(acc[mt][nt], ah[mt], bh[nt]);
        }
        __syncthreads();
    }

    int g = lane >> 2, t4 = lane & 3;
    #pragma unroll
    for (int mt = 0; mt < 2; mt++) {
        int r_lo = row0 + m_base + mt*16 + g;
        int r_hi = r_lo + 8;
        float rv_lo = rowv[r_lo];
        float rv_hi = rowv[r_hi];
        #pragma unroll
        for (int nt = 0; nt < 8; nt++) {
            int c = col0 + n_base + nt*8 + 2*t4;
            float cv0 = colv[c], cv1 = colv[c+1];
            float d00 = fmaf(alpha, acc[mt][nt][0], rv_lo + cv0);
            float d01 = fmaf(alpha, acc[mt][nt][1], rv_lo + cv1);
            float d10 = fmaf(alpha, acc[mt][nt][2], rv_hi + cv0);
            float d11 = fmaf(alpha, acc[mt][nt][3], rv_hi + cv1);
            if (nt < 4) {     // even 32-col block: store reciprocal (MUFU overlaps mma)
                d00 = rcp_approx(d00); d01 = rcp_approx(d01);
                d10 = rcp_approx(d10); d11 = rcp_approx(d11);
            }
            *(float2*)(Out + (size_t)r_lo*out_ld + c) = make_float2(d00, d01);
            *(float2*)(Out + (size_t)r_hi*out_ld + c) = make_float2(d10, d11);
        }
    }
}

// ================= attention (conflict-free smem, float4 dots) =================
#define APAD 260
__global__ void __launch_bounds__(256) attn_kernel() {
    __shared__ float qs[16][APAD], ks[16][APAD];
    __shared__ float att[16][16];
    int x = blockIdx.x;
    int b = x >> 10;
    int s = x & (HWp - 1);
    size_t base = ((size_t)(b*TT)*HWp + s)*CC;
    const size_t tstr = (size_t)HWp*CC;
    int tid = threadIdx.x;
    for (int e = tid; e < 16*256; e += 256) {
        int t = e >> 8, c = e & 255;
        qs[t][c] = g_q[base + (size_t)t*tstr + c];
        ks[t][c] = g_k[base + (size_t)t*tstr + c];
    }
    __syncthreads();
    int i = tid >> 4, j = tid & 15;
    float acc = 0.f;
    #pragma unroll 8
    for (int c4 = 0; c4 < 64; c4++) {
        float4 a = *(const float4*)&qs[i][c4*4];
        float4 bb = *(const float4*)&ks[j][c4*4];
        acc = fmaf(a.x, bb.x, acc); acc = fmaf(a.y, bb.y, acc);
        acc = fmaf(a.z, bb.z, acc); acc = fmaf(a.w, bb.w, acc);
    }
    att[i][j] = acc * 0.0625f;
    __syncthreads();
    if (tid < 16) {
        float m = -3.4e38f;
        for (int jj = 0; jj < 16; jj++) m = fmaxf(m, att[tid][jj]);
        float ssum = 0.f;
        for (int jj = 0; jj < 16; jj++) { float e = expf(att[tid][jj]-m); att[tid][jj] = e; ssum += e; }
        float r = 1.0f/ssum;
        for (int jj = 0; jj < 16; jj++) att[tid][jj] *= r;
    }
    __syncthreads();
    int c = tid;
    float vv[16];
    #pragma unroll
    for (int tk = 0; tk < 16; tk++) vv[tk] = g_v[base + (size_t)tk*tstr + c];
    #pragma unroll
    for (int tq = 0; tq < 16; tq++) {
        float o = 0.f;
        #pragma unroll
        for (int tk = 0; tk < 16; tk++) o += att[tq][tk]*vv[tk];
        size_t oi = base + (size_t)tq*tstr + c;
        split16(o*SXV, &g_p1h[oi], &g_p1l[oi]);
    }
}

__global__ void add_diff_kernel() {
    int p = blockIdx.x, c = threadIdx.x;
    size_t idx = (size_t)p*CC + c;
    int t = (p / HWp) % TT;
    float d = 0.f;
    if (t > 0) d = g_zp[idx] - g_zp[idx - (size_t)HWp*CC];
    float v = g_q[idx] + d;
    g_q[idx] = v;
    g_p1h[idx] = __float2half_rn(v*SXV);
    float s = v*v;
    #pragma unroll
    for (int o = 16; o; o >>= 1) s += __shfl_xor_sync(0xffffffffu, s, o);
    __shared__ float red[8];
    if ((c & 31) == 0) red[c >> 5] = s;
    __syncthreads();
    if (c == 0) {
        float tt = 0.f;
        #pragma unroll
        for (int j = 0; j < 8; j++) tt += red[j];
        g_xsq[NN + p] = tt;
    }
}

__global__ void rowsq_kernel(const float* __restrict__ X) {
    int warp = threadIdx.x >> 5, lane = threadIdx.x & 31;
    int row = blockIdx.x*8 + warp;
    const float* r = X + (size_t)row*CC;
    float s = 0.f;
    for (int c = lane; c < CC; c += 32) s += r[c]*r[c];
    #pragma unroll
    for (int o = 16; o; o >>= 1) s += __shfl_down_sync(0xffffffffu, s, o);
    if (!lane) g_xsq[row] = s;
}

// warp-per-row reduce in iv-domain. even j (32-col block) holds iv, odd j holds d.
__global__ void __launch_bounds__(256) vq_reduce_kernel(int branch, const float* __restrict__ X,
                                                        const float* __restrict__ EMB) {
    __shared__ float sacc[1024];
    int tid = threadIdx.x, w = tid >> 5, lane = tid & 31;
    for (int i = tid; i < 1024; i += 256) sacc[i] = 0.f;
    __syncthreads();
    int row0 = blockIdx.x * 64;
    float acc[32];
    #pragma unroll
    for (int j = 0; j < 32; j++) acc[j] = 0.f;
    for (int rr = 0; rr < 8; rr++) {
        int row = row0 + w*8 + rr;
        const float* dr = g_dist + (size_t)row*KCB;
        float inv[32];
        float lsum = 0.f, m1v = 0.f, m2v = 0.f; int i1 = 0;
        #pragma unroll
        for (int j = 0; j < 32; j++) {
            float v = dr[j*32 + lane];
            float iv = (j & 1) ? rcp_approx(v) : v;   // odd block stored d -> rcp here
            inv[j] = iv; lsum += iv;
            if (iv > m1v) { m2v = m1v; m1v = iv; i1 = j*32 + lane; }
            else m2v = fmaxf(m2v, iv);
        }
        #pragma unroll
        for (int o = 16; o; o >>= 1) {
            lsum += __shfl_xor_sync(0xffffffffu, lsum, o);
            float o1 = __shfl_xor_sync(0xffffffffu, m1v, o);
            int   oi = __shfl_xor_sync(0xffffffffu, i1, o);
            float o2 = __shfl_xor_sync(0xffffffffu, m2v, o);
            if (o1 > m1v || (o1 == m1v && oi < i1)) { m2v = fmaxf(m1v, o2); m1v = o1; i1 = oi; }
            else m2v = fmaxf(m2v, o1);
        }
        int idxf = i1;
        float d1 = rcp_approx(m1v);
        float d2 = rcp_approx(m2v);
        if (d2 - d1 <= REFINE_TH) {
            float xr[8];
            #pragma unroll
            for (int k = 0; k < 8; k++) xr[k] = X[(size_t)row*CC + lane + 32*k];
            float sA = g_xsq[branch*NN + row];
            float thr_iv = rcp_approx(d1 + REFINE_TH) * (1.0f - 2e-6f);
            float bestd = 3.4e38f; int besti = 0;
            for (int j = 0; j < 32; j++) {
                unsigned bal = __ballot_sync(0xffffffffu, inv[j] >= thr_iv);
                while (bal) {
                    int src = __ffs(bal) - 1; bal &= bal - 1;
                    int cidx = j*32 + src;
                    const float* er = EMB + (size_t)cidx*CC;
                    float dot = 0.f;
                    #pragma unroll
                    for (int k = 0; k < 8; k++) dot = fmaf(xr[k], er[lane + 32*k], dot);
                    #pragma unroll
                    for (int o = 16; o; o >>= 1) dot += __shfl_xor_sync(0xffffffffu, dot, o);
                    float de = fmaf(-2.f, dot, sA + g_embsq[branch*KCB + cidx]);
                    if (de < bestd) { bestd = de; besti = cidx; }
                }
            }
            idxf = besti;
        }
        if (lane == 0) {
            g_idx[branch*NN + row] = idxf;
            atomicAdd(&g_hist[branch*KCB + idxf], 1);
        }
        float irs = 1.0f/lsum;
        #pragma unroll
        for (int j = 0; j < 32; j++) acc[j] += inv[j]*irs;
    }
    #pragma unroll
    for (int j = 0; j < 32; j++) atomicAdd(&sacc[j*32 + lane], acc[j]);
    __syncthreads();
    for (int i = tid; i < 1024; i += 256) atomicAdd(&g_avg[branch*KCB + i], sacc[i]);
}

__global__ void assemble_kernel(const float* __restrict__ emb_s,
                                const float* __restrict__ emb_t,
                                float* __restrict__ out) {
    __shared__ float tl[32][33];
    __shared__ float mred[256];
    int b = blockIdx.z, c0 = blockIdx.y*32, s0 = blockIdx.x*32;
    int tx = threadIdx.x, ty = threadIdx.y;
    float lm = 0.f;
    #pragma unroll
    for (int i = 0; i < 4; i++) {
        int th = s0 + ty + i*8;
        int p = b*THW + th;
        int is = g_idx[p], it = g_idx[NN + p];
        int c = c0 + tx;
        float zpv = g_zp[(size_t)p*CC + c];
        float zq  = emb_t[(size_t)it*CC + c] + emb_s[(size_t)is*CC + c];
        float d = zq - zpv;
        lm += d*d;
        tl[ty + i*8][tx] = zpv + d;
    }
    int tid = ty*32 + tx;
    mred[tid] = lm;
    __syncthreads();
    for (int s = 128; s; s >>= 1) { if (tid < s) mred[tid] += mred[tid+s]; __syncthreads(); }
    if (tid == 0) atomicAdd(&g_mse, (double)mred[0]);
    #pragma unroll
    for (int i = 0; i < 4; i++) {
        int c  = c0 + ty + i*8;
        int th = s0 + tx;
        out[((size_t)(b*CC + c))*THW + th] = tl[tx][ty + i*8];
    }
}

__global__ void ind_write_kernel(float* __restrict__ out) {
    int gid = blockIdx.x*256 + threadIdx.x;
    int br = gid >> 16;
    int o  = gid & (NN - 1);
    int b = o / (TT*HWp);
    int rem = o - b*(TT*HWp);
    int t = rem / HWp;
    int s = rem & (HWp - 1);
    int src = (t*BB + b)*HWp + s;
    out[(br ? OFF_INDT : OFF_INDS) + o] = (float)g_idx[br*NN + src];
}

__global__ void __launch_bounds__(1024) finalize_kernel(float* __restrict__ out) {
    __shared__ double sd[1024];
    int t = threadIdx.x;
    if (t == 0) out[OFF_LOSS] = (float)(1.25 * g_mse / ((double)NN * (double)CC));
    for (int br = 0; br < 2; br++) {
        double e = (double)g_hist[br*KCB + t] / (double)NN;
        sd[t] = e * log(e + 1e-10);
        __syncthreads();
        for (int s = 512; s; s >>= 1) { if (t < s) sd[t] += sd[t+s]; __syncthreads(); }
        if (t == 0) out[br == 0 ? OFF_PERPS : OFF_PERPT] = (float)exp(-sd[0]);
        __syncthreads();
    }
    double kl[2];
    for (int br = 0; br < 2; br++) {
        double a = (double)g_avg[br*KCB + t] / (double)NN;
        sd[t] = a; __syncthreads();
        for (int s = 512; s; s >>= 1) { if (t < s) sd[t] = fmax(sd[t], sd[t+s]); __syncthreads(); }
        double m = sd[0]; __syncthreads();
        sd[t] = exp(a - m); __syncthreads();
        for (int s = 512; s; s >>= 1) { if (t < s) sd[t] += sd[t+s]; __syncthreads(); }
        double Z = sd[0]; __syncthreads();
        sd[t] = a; __syncthreads();
        for (int s = 512; s; s >>= 1) { if (t < s) sd[t] += sd[t+s]; __syncthreads(); }
        double SA = sd[0]; __syncthreads();
        double lse = m + log(Z);
        double tgt = 1.0 / (double)KCB;
        kl[br] = tgt * (log(tgt) + lse - SA / (double)KCB);
    }
    if (t == 0) out[OFF_LOSS2] = (float)(0.1 * (kl[0] + kl[1]));
}

// ================= host =================

extern "C" void kernel_launch(void* const* d_in, const int* in_sizes, int n_in,
                              void* d_out, int out_size) {
    (void)in_sizes; (void)n_in; (void)out_size;
    const float* z     = (const float*)d_in[0];
    const float* emb_s = (const float*)d_in[1];
    const float* emb_t = (const float*)d_in[2];
    const float* gamma = (const float*)d_in[3];
    const float* beta  = (const float*)d_in[4];
    const float* wq = (const float*)d_in[5];
    const float* bq = (const float*)d_in[6];
    const float* wk = (const float*)d_in[7];
    const float* bk = (const float*)d_in[8];
    const float* wv = (const float*)d_in[9];
    const float* bv = (const float*)d_in[10];
    const float* wp = (const float*)d_in[11];
    const float* bp = (const float*)d_in[12];
    float* out = (float*)d_out;

    float *p_zp, *p_q, *p_k, *p_v, *p_dist, *p_embsq, *p_xsq;
    __half *p1h, *p1l, *p2h, *pwh, *pwl, *pebh;
    cudaGetSymbolAddress((void**)&p_zp, g_zp);
    cudaGetSymbolAddress((void**)&p_q,  g_q);
    cudaGetSymbolAddress((void**)&p_k,  g_k);
    cudaGetSymbolAddress((void**)&p_v,  g_v);
    cudaGetSymbolAddress((void**)&p_dist, g_dist);
    cudaGetSymbolAddress((void**)&p_embsq, g_embsq);
    cudaGetSymbolAddress((void**)&p_xsq, g_xsq);
    cudaGetSymbolAddress((void**)&p1h, g_p1h);
    cudaGetSymbolAddress((void**)&p1l, g_p1l);
    cudaGetSymbolAddress((void**)&p2h, g_p2h);
    cudaGetSymbolAddress((void**)&pwh, g_wh);
    cudaGetSymbolAddress((void**)&pwl, g_wl);
    cudaGetSymbolAddress((void**)&pebh, g_ebh);

    cudaFuncSetAttribute(gemm3fp16, cudaFuncAttributeMaxDynamicSharedMemorySize, GSM3);
    cudaFuncSetAttribute(gemm_dist, cudaFuncAttributeMaxDynamicSharedMemorySize, GSM1);

    zero_kernel<<<8, 256>>>();
    embsplit_kernel<<<2*KCB, 256>>>(emb_s, emb_t);
    wsplit_kernel<<<4*CC*CC/256, 256>>>(wq, wk, wv, wp);
    gn_partial<<<2048, 256>>>(z);
    gn_final<<<1, 64>>>();
    transpose_norm_kernel<<<dim3(THW/32, CC/32, BB), dim3(32, 8)>>>(z, gamma, beta);
    rowsq_kernel<<<NN/8, 256>>>(p_zp);

    gemm3fp16<<<dim3(CC/128, NN/128), 256, GSM3>>>(p1h, p1l, pwh,           pwl,           bq, p_q, CC, ALPHA_CONV);
    gemm3fp16<<<dim3(CC/128, NN/128), 256, GSM3>>>(p1h, p1l, pwh + CC*CC,   pwl + CC*CC,   bk, p_k, CC, ALPHA_CONV);
    gemm3fp16<<<dim3(CC/128, NN/128), 256, GSM3>>>(p1h, p1l, pwh + 2*CC*CC, pwl + 2*CC*CC, bv, p_v, CC, ALPHA_CONV);

    attn_kernel<<<BB*HWp, 256>>>();
    gemm3fp16<<<dim3(CC/128, NN/128), 256, GSM3>>>(p1h, p1l, pwh + 3*CC*CC, pwl + 3*CC*CC, bp, p_q, CC, ALPHA_CONV);
    add_diff_kernel<<<NN, 256>>>();

    gemm_dist<<<dim3(KCB/128, NN/128), 256, GSM1>>>(p2h, pebh, p_embsq, p_xsq, p_dist, KCB, ALPHA_DIST);
    vq_reduce_kernel<<<NN/64, 256>>>(0, p_zp, emb_s);

    gemm_dist<<<dim3(KCB/128, NN/128), 256, GSM1>>>(p1h, pebh + (size_t)KCB*CC, p_embsq + KCB, p_xsq + NN, p_dist, KCB, ALPHA_DIST);
    vq_reduce_kernel<<<NN/64, 256>>>(1, p_q, emb_t);

    assemble_kernel<<<dim3(THW/32, CC/32, BB), dim3(32, 8)>>>(emb_s, emb_t, out);
    ind_write_kernel<<<2*NN/256, 256>>>(out);
    finalize_kernel<<<1, 1024>>>(out);
}